// round 3
// baseline (speedup 1.0000x reference)
#include <cuda_runtime.h>

// Problem constants (fixed by the reference): N=50000, E=250000, D=300, L=5
#define D_    300
#define TWOD_ 600
#define NMAX  50000
#define EMAX  250000
#define STAT_BLOCKS 200

// ---- static scratch (no allocations allowed) ----
__device__ float g_h [NMAX * D_];     // node features (post-BN/relu)
__device__ float g_z [NMAX * D_];     // (1+eps)*h, accumulates messages
__device__ float g_h1[NMAX * TWOD_];  // hidden after GEMM1
__device__ float g_z2[NMAX * D_];     // after GEMM2
__device__ float g_ps[STAT_BLOCKS * TWOD_]; // partial sums
__device__ float g_pq[STAT_BLOCKS * TWOD_]; // partial sums of squares
__device__ float g_bnA[TWOD_];        // per-column scale  = g*rsqrt(var+eps)
__device__ float g_bnB[TWOD_];        // per-column shift  = b - mean*scale

// ============================================================
// Atom encoder: h[n,d] = sum_i atom_emb[i, x[n,i], d]; also z = (1+eps0)*h
// ============================================================
__global__ void k_atom(const int* __restrict__ x, const float* __restrict__ emb,
                       const float* __restrict__ eps, int n)
{
    int idx = blockIdx.x * blockDim.x + threadIdx.x;
    if (idx >= n * D_) return;
    int node = idx / D_;
    int d    = idx - node * D_;
    const int* xr = x + node * 9;
    float s = 0.f;
#pragma unroll
    for (int i = 0; i < 9; i++)
        s += emb[(i * 128 + xr[i]) * D_ + d];
    g_h[idx] = s;
    g_z[idx] = (1.f + eps[0]) * s;
}

// ============================================================
// Edge phase: msg = relu(h[src] + bond_emb_sum); atomicAdd into z[dst]
// One thread per (edge, dim). Skips the atomic when msg==0 (post-relu).
// ============================================================
__global__ void k_edge(const int* __restrict__ ei, const int* __restrict__ ea,
                       const float* __restrict__ bond, int E_, int layer)
{
    int idx = blockIdx.x * blockDim.x + threadIdx.x;
    if (idx >= E_ * D_) return;
    int e = idx / D_;
    int d = idx - e * D_;
    int src = ei[e];
    int dst = ei[E_ + e];
    const float* bl = bond + layer * 3 * 16 * D_;
    int a0 = ea[e * 3 + 0], a1 = ea[e * 3 + 1], a2 = ea[e * 3 + 2];
    float ev = bl[a0 * D_ + d] + bl[(16 + a1) * D_ + d] + bl[(32 + a2) * D_ + d];
    float m = g_h[src * D_ + d] + ev;
    if (m > 0.f) atomicAdd(&g_z[dst * D_ + d], m);
}

// ============================================================
// Tiled fp32 GEMM: C[M,NC] = op(A)[M,K] @ B[K,NC] + bias
// op(A) = relu(A*sA + sB) per-column when sA != nullptr (fused BN+relu)
// BM=128, BN=64, BK=8, 256 threads, 8x4 per thread, float4 paths.
// ============================================================
__global__ void __launch_bounds__(256) k_gemm(
    const float* __restrict__ A, const float* __restrict__ Bw,
    const float* __restrict__ bias, float* __restrict__ C,
    int M, int K, int NC,
    const float* __restrict__ sA, const float* __restrict__ sB)
{
    __shared__ float As[8][128];
    __shared__ float Bs[8][64];
    const int tid = threadIdx.x;
    const int bm = blockIdx.y * 128;
    const int bn = blockIdx.x * 64;
    const int ty = tid >> 4;          // 0..15 -> 8 rows each
    const int tx = tid & 15;          // 0..15 -> 4 cols each
    const int ar = tid >> 1;          // 0..127 (A tile row)
    const int ac = (tid & 1) << 2;    // 0 or 4 (A tile k offset, float4)
    const int br = tid >> 5;          // 0..7   (B tile k row)
    const int bc = (tid & 31) << 1;   // 0..62  (B tile col, float2)

    float acc[8][4];
#pragma unroll
    for (int i = 0; i < 8; i++)
#pragma unroll
        for (int j = 0; j < 4; j++) acc[i][j] = 0.f;

    const int  arow = bm + ar;
    const bool arOk = arow < M;
    const float* Ap = A + (size_t)arow * K;
    const bool bcOk = (bn + bc) < NC;       // NC even -> all-or-nothing float2
    const bool fuse = (sA != nullptr);
    const int kt = (K + 7) >> 3;

    for (int t = 0; t < kt; ++t) {
        int k0 = t << 3;
        // --- load A tile (rows x 8k), optional fused BN+relu per k-column ---
        float4 av = make_float4(0.f, 0.f, 0.f, 0.f);
        int ka = k0 + ac;                  // multiple of 4; K%4==0 -> all-or-nothing
        if (arOk && ka < K) {
            av = *(const float4*)(Ap + ka);
            if (fuse) {
                float4 s4 = *(const float4*)(sA + ka);
                float4 h4 = *(const float4*)(sB + ka);
                av.x = fmaxf(fmaf(av.x, s4.x, h4.x), 0.f);
                av.y = fmaxf(fmaf(av.y, s4.y, h4.y), 0.f);
                av.z = fmaxf(fmaf(av.z, s4.z, h4.z), 0.f);
                av.w = fmaxf(fmaf(av.w, s4.w, h4.w), 0.f);
            }
        }
        As[ac + 0][ar] = av.x;
        As[ac + 1][ar] = av.y;
        As[ac + 2][ar] = av.z;
        As[ac + 3][ar] = av.w;

        // --- load B tile (8k x 64) ---
        float2 bv = make_float2(0.f, 0.f);
        int kb = k0 + br;
        if (kb < K && bcOk)
            bv = *(const float2*)(Bw + (size_t)kb * NC + bn + bc);
        Bs[br][bc + 0] = bv.x;
        Bs[br][bc + 1] = bv.y;

        __syncthreads();
#pragma unroll
        for (int kk = 0; kk < 8; ++kk) {
            float a_r[8], b_r[4];
            *(float4*)&a_r[0] = *(const float4*)&As[kk][ty << 3];
            *(float4*)&a_r[4] = *(const float4*)&As[kk][(ty << 3) + 4];
            *(float4*)&b_r[0] = *(const float4*)&Bs[kk][tx << 2];
#pragma unroll
            for (int i = 0; i < 8; i++)
#pragma unroll
                for (int j = 0; j < 4; j++)
                    acc[i][j] = fmaf(a_r[i], b_r[j], acc[i][j]);
        }
        __syncthreads();
    }

    // --- epilogue: +bias, predicated float4 stores ---
    int c0 = bn + (tx << 2);
    if (c0 < NC) {                         // NC%4==0 -> all-or-nothing
        float4 bb = *(const float4*)(bias + c0);
#pragma unroll
        for (int i = 0; i < 8; i++) {
            int r = bm + (ty << 3) + i;
            if (r < M) {
                float4 o;
                o.x = acc[i][0] + bb.x;
                o.y = acc[i][1] + bb.y;
                o.z = acc[i][2] + bb.z;
                o.w = acc[i][3] + bb.w;
                *(float4*)(C + (size_t)r * NC + c0) = o;
            }
        }
    }
}

// ============================================================
// Column stats: per-block partial sum / sumsq into fixed slots (no zeroing)
// blockDim.x == C (300 or 600); coalesced row-major reads.
// ============================================================
__global__ void k_stats(const float* __restrict__ X, int M, int C)
{
    int c = threadIdx.x;
    int rows = (M + gridDim.x - 1) / gridDim.x;
    int r0 = blockIdx.x * rows;
    int r1 = min(M, r0 + rows);
    float s = 0.f, q = 0.f;
    for (int r = r0; r < r1; ++r) {
        float v = X[(size_t)r * C + c];
        s += v;
        q += v * v;
    }
    g_ps[blockIdx.x * C + c] = s;
    g_pq[blockIdx.x * C + c] = q;
}

// Finalize BN affine: A = g*rsqrt(var+eps), B = b - mean*A
__global__ void k_finalize(const float* __restrict__ g, const float* __restrict__ b,
                           int M, int C)
{
    int c = threadIdx.x;
    float s = 0.f, q = 0.f;
#pragma unroll 4
    for (int i = 0; i < STAT_BLOCKS; i++) {
        s += g_ps[i * C + c];
        q += g_pq[i * C + c];
    }
    float mean = s / (float)M;
    float var  = q / (float)M - mean * mean;
    float a = g[c] * rsqrtf(var + 1e-5f);
    g_bnA[c] = a;
    g_bnB[c] = fmaf(-mean, a, b[c]);
}

// ============================================================
// Outer BN apply (+relu) fused with next layer's z=(1+eps)*h init.
// Last layer writes straight to d_out (no relu).
// ============================================================
__global__ void k_apply(const float* __restrict__ eps, int next_l, int do_relu,
                        int n, float* __restrict__ out)
{
    int idx = blockIdx.x * blockDim.x + threadIdx.x;
    if (idx >= n * D_) return;
    int c = idx % D_;
    float v = fmaf(g_z2[idx], g_bnA[c], g_bnB[c]);
    if (do_relu) v = fmaxf(v, 0.f);
    if (out) {
        out[idx] = v;
    } else {
        g_h[idx] = v;
        g_z[idx] = (1.f + eps[next_l]) * v;
    }
}

// ============================================================
// Launch
// ============================================================
extern "C" void kernel_launch(void* const* d_in, const int* in_sizes, int n_in,
                              void* d_out, int out_size)
{
    const int*   x     = (const int*)  d_in[0];
    const int*   ei    = (const int*)  d_in[1];
    const int*   ea    = (const int*)  d_in[2];
    const float* atom  = (const float*)d_in[3];
    const float* bond  = (const float*)d_in[4];
    const float* eps   = (const float*)d_in[5];
    const float* W1    = (const float*)d_in[6];
    const float* b1    = (const float*)d_in[7];
    const float* g1    = (const float*)d_in[8];
    const float* be1   = (const float*)d_in[9];
    const float* W2    = (const float*)d_in[10];
    const float* b2    = (const float*)d_in[11];
    const float* gamma = (const float*)d_in[12];
    const float* beta  = (const float*)d_in[13];
    float* out = (float*)d_out;

    const int N = in_sizes[0] / 9;
    const int E = in_sizes[1] / 2;

    float *ph, *ph1, *pz, *pz2, *pA, *pB;
    cudaGetSymbolAddress((void**)&ph,  g_h);
    cudaGetSymbolAddress((void**)&pz,  g_z);
    cudaGetSymbolAddress((void**)&ph1, g_h1);
    cudaGetSymbolAddress((void**)&pz2, g_z2);
    cudaGetSymbolAddress((void**)&pA,  g_bnA);
    cudaGetSymbolAddress((void**)&pB,  g_bnB);

    const int TPB = 256;
    const int node_grid = (N * D_ + TPB - 1) / TPB;
    const int edge_grid = (E * D_ + TPB - 1) / TPB;
    const dim3 gemm1_grid((TWOD_ + 63) / 64, (N + 127) / 128);
    const dim3 gemm2_grid((D_ + 63) / 64,   (N + 127) / 128);

    // h = AtomEncoder(x); z = (1+eps[0])*h
    k_atom<<<node_grid, TPB>>>(x, atom, eps, N);

    for (int l = 0; l < 5; ++l) {
        // z += sum_{e: dst=v} relu(h[src] + bond_emb_l(edge_attr))
        k_edge<<<edge_grid, TPB>>>(ei, ea, bond, E, l);
        // h1 = z @ W1[l] + b1[l]
        k_gemm<<<gemm1_grid, TPB>>>(pz, W1 + (size_t)l * D_ * TWOD_,
                                    b1 + l * TWOD_, ph1,
                                    N, D_, TWOD_, nullptr, nullptr);
        // BN1 stats + affine
        k_stats<<<STAT_BLOCKS, TWOD_>>>(ph1, N, TWOD_);
        k_finalize<<<1, TWOD_>>>(g1 + l * TWOD_, be1 + l * TWOD_, N, TWOD_);
        // z2 = relu(BN1(h1)) @ W2[l] + b2[l]   (BN+relu fused into A-load)
        k_gemm<<<gemm2_grid, TPB>>>(ph1, W2 + (size_t)l * TWOD_ * D_,
                                    b2 + l * D_, pz2,
                                    N, TWOD_, D_, pA, pB);
        // BN2 stats + affine
        k_stats<<<STAT_BLOCKS, D_>>>(pz2, N, D_);
        k_finalize<<<1, D_>>>(gamma + l * D_, beta + l * D_, N, D_);
        // h = BN2(z2) (+relu if not last); also z = (1+eps[l+1])*h for next layer
        if (l < 4)
            k_apply<<<node_grid, TPB>>>(eps, l + 1, 1, N, nullptr);
        else
            k_apply<<<node_grid, TPB>>>(eps, 0, 0, N, out);
    }
}

// round 5
// speedup vs baseline: 1.0363x; 1.0363x over previous
#include <cuda_runtime.h>
#include <cstdint>

// Problem constants: N=50000, E=250000, D=300, L=5
#define D_    300
#define TWOD_ 600
#define NMAX  50000
#define STAT_BLOCKS 200
#define KPAD1 320   // 300 -> 10 chunks of 32
#define KPAD2 608   // 600 -> 19 chunks of 32
#define NCP1  640   // 600 -> 5 tiles of 128 (zero-padded rows)
#define NCP2  384   // 300 -> 3 tiles of 128

// GEMM tiling
#define BM 128
#define BN 128
#define BK 32
#define STR 40                 // smem row stride in floats (32 data + 8 pad)
#define TSZ (128 * STR)        // floats per tile (5120)
#define AHO 0
#define ALO TSZ
#define BHO (2 * TSZ)
#define BLO (3 * TSZ)
#define BUFSZ (4 * TSZ)        // floats per stage (20480)
#define GEMM_SMEM (2 * BUFSZ * 4)  // bytes (163840)

// ---- static scratch (no allocations allowed) ----
__device__ float g_h [NMAX * D_];
__device__ float g_z [NMAX * D_];
__device__ float g_h1[NMAX * TWOD_];
__device__ float g_z2[NMAX * D_];
__device__ float g_ps[STAT_BLOCKS * TWOD_];
__device__ float g_pq[STAT_BLOCKS * TWOD_];
__device__ float g_bnA[TWOD_];
__device__ float g_bnB[TWOD_];
// pre-transposed + tf32-split + k-permuted + zero-padded weights
__device__ float g_w1h[NCP1 * KPAD1];
__device__ float g_w1l[NCP1 * KPAD1];
__device__ float g_w2h[NCP2 * KPAD2];
__device__ float g_w2l[NCP2 * KPAD2];

// ============================================================
// helpers (all baseline PTX — safe under virtual arch compute_103)
// ============================================================
__device__ __forceinline__ uint32_t smem_u32(const void* p) {
    uint32_t a;
    asm("{ .reg .u64 t; cvta.to.shared.u64 t, %1; cvt.u32.u64 %0, t; }"
        : "=r"(a) : "l"(p));
    return a;
}
__device__ __forceinline__ void cp16(uint32_t dst, const void* src) {
    asm volatile("cp.async.cg.shared.global [%0], [%1], 16;"
                 :: "r"(dst), "l"(src) : "memory");
}
__device__ __forceinline__ void cp_commit() {
    asm volatile("cp.async.commit_group;" ::: "memory");
}
__device__ __forceinline__ void cp_wait0() {
    asm volatile("cp.async.wait_group 0;" ::: "memory");
}
// 3xTF32 split: a = hi + lo, both tf32 bit patterns
__device__ __forceinline__ void tf32s(float a, uint32_t& hb, uint32_t& lb) {
    asm("cvt.rna.tf32.f32 %0, %1;" : "=r"(hb) : "f"(a));
    float d = a - __uint_as_float(hb);
    asm("cvt.rna.tf32.f32 %0, %1;" : "=r"(lb) : "f"(d));
}
// m16n8k8 tf32 MMA (row.col), D=C accumulate in fp32
__device__ __forceinline__ void mma8(float* c,
                                     uint32_t a0, uint32_t a1, uint32_t a2, uint32_t a3,
                                     uint32_t b0, uint32_t b1) {
    asm volatile(
        "mma.sync.aligned.m16n8k8.row.col.f32.tf32.tf32.f32 "
        "{%0,%1,%2,%3}, {%4,%5,%6,%7}, {%8,%9}, {%0,%1,%2,%3};"
        : "+f"(c[0]), "+f"(c[1]), "+f"(c[2]), "+f"(c[3])
        : "r"(a0), "r"(a1), "r"(a2), "r"(a3), "r"(b0), "r"(b1));
}

// ============================================================
// Atom encoder
// ============================================================
__global__ void k_atom(const int* __restrict__ x, const float* __restrict__ emb,
                       const float* __restrict__ eps, int n)
{
    int idx = blockIdx.x * blockDim.x + threadIdx.x;
    if (idx >= n * D_) return;
    int node = idx / D_;
    int d    = idx - node * D_;
    const int* xr = x + node * 9;
    float s = 0.f;
#pragma unroll
    for (int i = 0; i < 9; i++)
        s += emb[(i * 128 + xr[i]) * D_ + d];
    g_h[idx] = s;
    g_z[idx] = (1.f + eps[0]) * s;
}

// ============================================================
// Edge phase
// ============================================================
__global__ void k_edge(const int* __restrict__ ei, const int* __restrict__ ea,
                       const float* __restrict__ bond, int E_, int layer)
{
    int idx = blockIdx.x * blockDim.x + threadIdx.x;
    if (idx >= E_ * D_) return;
    int e = idx / D_;
    int d = idx - e * D_;
    int src = ei[e];
    int dst = ei[E_ + e];
    const float* bl = bond + layer * 3 * 16 * D_;
    int a0 = ea[e * 3 + 0], a1 = ea[e * 3 + 1], a2 = ea[e * 3 + 2];
    float ev = bl[a0 * D_ + d] + bl[(16 + a1) * D_ + d] + bl[(32 + a2) * D_ + d];
    float m = g_h[src * D_ + d] + ev;
    if (m > 0.f) atomicAdd(&g_z[dst * D_ + d], m);
}

// ============================================================
// Weight prep: Wt[n, kperm(k)] = tf32_split(W[k, n]); zero pad k>=K, n>=NC
// kperm reorders within each 8-group so fragment loads are lds.64
// ============================================================
__global__ void k_wprep(const float* __restrict__ W, float* __restrict__ Wh,
                        float* __restrict__ Wl, int K, int NC, int Kpad, int NCpad)
{
    int idx = blockIdx.x * blockDim.x + threadIdx.x;
    if (idx >= NCpad * Kpad) return;
    int n  = idx / Kpad;
    int kp = idx - n * Kpad;
    float v = (kp < K && n < NC) ? W[kp * NC + n] : 0.f;
    uint32_t hb, lb;
    tf32s(v, hb, lb);
    int kperm = (kp & ~7) | ((kp & 3) << 1) | ((kp & 7) >> 2);
    Wh[n * Kpad + kperm] = __uint_as_float(hb);
    Wl[n * Kpad + kperm] = __uint_as_float(lb);
}

// ============================================================
// 3xTF32 mma.sync GEMM: C[M,NC] = op(A)[M,K] @ W[K,NC] + bias
//   B given pre-transposed/split/permuted/padded: [NCpad, Kpad] K-major.
//   op(A) = relu(A*sA + sB) per-k-column when sA != nullptr.
// 128x128x32 tiles, 8 warps (2x4), double-buffered, 1 sync/chunk.
// ============================================================
__global__ void __launch_bounds__(256, 1) k_gemm_mma(
    const float* __restrict__ A,
    const float* __restrict__ Bh, const float* __restrict__ Bl,
    const float* __restrict__ bias, float* __restrict__ C,
    int M, int K, int Kpad, int NC,
    const float* __restrict__ sA, const float* __restrict__ sB)
{
    extern __shared__ float sm[];
    const int tid = threadIdx.x;
    const int wid = tid >> 5, lid = tid & 31;
    const int g = lid >> 2, t4 = lid & 3;
    const int wm = wid >> 2, wn = wid & 3;
    const int bm = blockIdx.y * BM, bn = blockIdx.x * BN;
    const int nch = Kpad / BK;
    const bool fuse = (sA != nullptr);

    // loader mapping: row lr (0..127), half lh selects 16 k-columns
    const int lr = tid >> 1;
    const int lh = tid & 1;
    const bool aOk = (bm + lr) < M;
    const float* Ap = A + (size_t)(bm + lr) * K;
    const size_t bRow = (size_t)(bn + lr) * Kpad + lh * 16;
    const uint32_t sm32 = smem_u32(sm);
    const uint32_t cpBH = sm32 + (uint32_t)((BHO + lr * STR + lh * 16) * 4);
    const uint32_t cpBL = sm32 + (uint32_t)((BLO + lr * STR + lh * 16) * 4);

    float acc[4][4][4];
#pragma unroll
    for (int i = 0; i < 4; i++)
#pragma unroll
        for (int j = 0; j < 4; j++)
#pragma unroll
            for (int k = 0; k < 4; k++) acc[i][j][k] = 0.f;

    float4 av[4];

    // ---- stage helpers as macros over locals ----
#define LOAD_A(K0)                                                        \
    {                                                                     \
        const int kkb = (K0) + lh * 16;                                   \
        _Pragma("unroll")                                                 \
        for (int q = 0; q < 4; ++q) {                                     \
            int ka = kkb + 4 * q;                                         \
            float4 v = make_float4(0.f, 0.f, 0.f, 0.f);                   \
            if (aOk && ka < K) {                                          \
                v = *(const float4*)(Ap + ka);                            \
                if (fuse) {                                               \
                    float4 s4 = *(const float4*)(sA + ka);                \
                    float4 h4 = *(const float4*)(sB + ka);                \
                    v.x = fmaxf(fmaf(v.x, s4.x, h4.x), 0.f);              \
                    v.y = fmaxf(fmaf(v.y, s4.y, h4.y), 0.f);              \
                    v.z = fmaxf(fmaf(v.z, s4.z, h4.z), 0.f);              \
                    v.w = fmaxf(fmaf(v.w, s4.w, h4.w), 0.f);              \
                }                                                         \
            }                                                             \
            av[q] = v;                                                    \
        }                                                                 \
    }

#define CP_B(BUFO, K0)                                                    \
    {                                                                     \
        const uint32_t bo4 = (uint32_t)((BUFO) * 4);                      \
        const float* sh = Bh + bRow + (K0);                               \
        const float* sl = Bl + bRow + (K0);                               \
        _Pragma("unroll")                                                 \
        for (int u = 0; u < 4; ++u) {                                     \
            cp16(cpBH + bo4 + u * 16, sh + u * 4);                        \
            cp16(cpBL + bo4 + u * 16, sl + u * 4);                        \
        }                                                                 \
    }

#define STORE_A(BUFO)                                                     \
    {                                                                     \
        float f[16];                                                      \
        *(float4*)&f[0]  = av[0];                                         \
        *(float4*)&f[4]  = av[1];                                         \
        *(float4*)&f[8]  = av[2];                                         \
        *(float4*)&f[12] = av[3];                                         \
        uint32_t hb[16], lb[16];                                          \
        _Pragma("unroll")                                                 \
        for (int i = 0; i < 16; ++i) tf32s(f[i], hb[i], lb[i]);           \
        uint4* dH = (uint4*)(sm + (BUFO) + AHO + lr * STR + lh * 16);     \
        uint4* dL = (uint4*)(sm + (BUFO) + ALO + lr * STR + lh * 16);     \
        dH[0] = make_uint4(hb[0], hb[4],  hb[1], hb[5]);                  \
        dH[1] = make_uint4(hb[2], hb[6],  hb[3], hb[7]);                  \
        dH[2] = make_uint4(hb[8], hb[12], hb[9], hb[13]);                 \
        dH[3] = make_uint4(hb[10],hb[14], hb[11],hb[15]);                 \
        dL[0] = make_uint4(lb[0], lb[4],  lb[1], lb[5]);                  \
        dL[1] = make_uint4(lb[2], lb[6],  lb[3], lb[7]);                  \
        dL[2] = make_uint4(lb[8], lb[12], lb[9], lb[13]);                 \
        dL[3] = make_uint4(lb[10],lb[14], lb[11],lb[15]);                 \
    }

    // ---- prologue: fill buffer 0 with chunk 0 ----
    LOAD_A(0);
    CP_B(0, 0);
    cp_commit();
    STORE_A(0);
    cp_wait0();
    __syncthreads();

    // ---- main loop: one __syncthreads per chunk ----
    for (int c = 0; c < nch; ++c) {
        const int bufc = (c & 1) * BUFSZ;
        const int bufn = ((c + 1) & 1) * BUFSZ;
        if (c + 1 < nch) {
            LOAD_A((c + 1) * BK);
            CP_B(bufn, (c + 1) * BK);
            cp_commit();
        }
        // ---- compute chunk c ----
        {
            const float* aH = sm + bufc + AHO;
            const float* aL = sm + bufc + ALO;
            const float* bH = sm + bufc + BHO;
            const float* bL = sm + bufc + BLO;
#pragma unroll
            for (int j = 0; j < 4; ++j) {
                const int ko = j * 8 + 2 * t4;
                uint2 fbh[4], fbl[4];
#pragma unroll
                for (int nt = 0; nt < 4; ++nt) {
                    const int n = wn * 32 + nt * 8 + g;
                    fbh[nt] = *(const uint2*)(bH + n * STR + ko);
                    fbl[nt] = *(const uint2*)(bL + n * STR + ko);
                }
#pragma unroll
                for (int mt = 0; mt < 4; ++mt) {
                    const int r0 = wm * 64 + mt * 16 + g;
                    uint2 h0 = *(const uint2*)(aH + r0 * STR + ko);
                    uint2 h1 = *(const uint2*)(aH + (r0 + 8) * STR + ko);
                    uint2 l0 = *(const uint2*)(aL + r0 * STR + ko);
                    uint2 l1 = *(const uint2*)(aL + (r0 + 8) * STR + ko);
#pragma unroll
                    for (int nt = 0; nt < 4; ++nt) {
                        mma8(acc[mt][nt], h0.x, h1.x, h0.y, h1.y, fbh[nt].x, fbh[nt].y);
                        mma8(acc[mt][nt], h0.x, h1.x, h0.y, h1.y, fbl[nt].x, fbl[nt].y);
                        mma8(acc[mt][nt], l0.x, l1.x, l0.y, l1.y, fbh[nt].x, fbh[nt].y);
                    }
                }
            }
        }
        if (c + 1 < nch) {
            STORE_A(bufn);
            cp_wait0();
        }
        __syncthreads();
    }

    // ---- epilogue: +bias, direct float2 stores ----
#pragma unroll
    for (int mt = 0; mt < 4; ++mt) {
        const int r0g = bm + wm * 64 + mt * 16 + g;
#pragma unroll
        for (int nt = 0; nt < 4; ++nt) {
            const int col = bn + wn * 32 + nt * 8 + 2 * t4;
            if (col < NC) {
                const float b0 = bias[col];
                const float b1 = bias[col + 1];
                const float* a4 = acc[mt][nt];
                if (r0g < M) {
                    float2 v = make_float2(a4[0] + b0, a4[1] + b1);
                    *(float2*)(C + (size_t)r0g * NC + col) = v;
                }
                if (r0g + 8 < M) {
                    float2 v = make_float2(a4[2] + b0, a4[3] + b1);
                    *(float2*)(C + (size_t)(r0g + 8) * NC + col) = v;
                }
            }
        }
    }
#undef LOAD_A
#undef CP_B
#undef STORE_A
}

// ============================================================
// Column stats + BN finalize + apply
// ============================================================
__global__ void k_stats(const float* __restrict__ X, int M, int C)
{
    int c = threadIdx.x;
    int rows = (M + gridDim.x - 1) / gridDim.x;
    int r0 = blockIdx.x * rows;
    int r1 = min(M, r0 + rows);
    float s = 0.f, q = 0.f;
    for (int r = r0; r < r1; ++r) {
        float v = X[(size_t)r * C + c];
        s += v;
        q += v * v;
    }
    g_ps[blockIdx.x * C + c] = s;
    g_pq[blockIdx.x * C + c] = q;
}

__global__ void k_finalize(const float* __restrict__ g, const float* __restrict__ b,
                           int M, int C)
{
    int c = threadIdx.x;
    float s = 0.f, q = 0.f;
#pragma unroll 4
    for (int i = 0; i < STAT_BLOCKS; i++) {
        s += g_ps[i * C + c];
        q += g_pq[i * C + c];
    }
    float mean = s / (float)M;
    float var  = q / (float)M - mean * mean;
    float a = g[c] * rsqrtf(var + 1e-5f);
    g_bnA[c] = a;
    g_bnB[c] = fmaf(-mean, a, b[c]);
}

__global__ void k_apply(const float* __restrict__ eps, int next_l, int do_relu,
                        int n, float* __restrict__ out)
{
    int idx = blockIdx.x * blockDim.x + threadIdx.x;
    if (idx >= n * D_) return;
    int c = idx % D_;
    float v = fmaf(g_z2[idx], g_bnA[c], g_bnB[c]);
    if (do_relu) v = fmaxf(v, 0.f);
    if (out) {
        out[idx] = v;
    } else {
        g_h[idx] = v;
        g_z[idx] = (1.f + eps[next_l]) * v;
    }
}

// ============================================================
// Launch
// ============================================================
extern "C" void kernel_launch(void* const* d_in, const int* in_sizes, int n_in,
                              void* d_out, int out_size)
{
    const int*   x     = (const int*)  d_in[0];
    const int*   ei    = (const int*)  d_in[1];
    const int*   ea    = (const int*)  d_in[2];
    const float* atom  = (const float*)d_in[3];
    const float* bond  = (const float*)d_in[4];
    const float* eps   = (const float*)d_in[5];
    const float* W1    = (const float*)d_in[6];
    const float* b1    = (const float*)d_in[7];
    const float* g1    = (const float*)d_in[8];
    const float* be1   = (const float*)d_in[9];
    const float* W2    = (const float*)d_in[10];
    const float* b2    = (const float*)d_in[11];
    const float* gamma = (const float*)d_in[12];
    const float* beta  = (const float*)d_in[13];
    float* out = (float*)d_out;

    const int N = in_sizes[0] / 9;
    const int E = in_sizes[1] / 2;

    float *ph1, *pz, *pz2, *pA, *pB;
    float *pw1h, *pw1l, *pw2h, *pw2l;
    cudaGetSymbolAddress((void**)&pz,   g_z);
    cudaGetSymbolAddress((void**)&ph1,  g_h1);
    cudaGetSymbolAddress((void**)&pz2,  g_z2);
    cudaGetSymbolAddress((void**)&pA,   g_bnA);
    cudaGetSymbolAddress((void**)&pB,   g_bnB);
    cudaGetSymbolAddress((void**)&pw1h, g_w1h);
    cudaGetSymbolAddress((void**)&pw1l, g_w1l);
    cudaGetSymbolAddress((void**)&pw2h, g_w2h);
    cudaGetSymbolAddress((void**)&pw2l, g_w2l);

    cudaFuncSetAttribute(k_gemm_mma, cudaFuncAttributeMaxDynamicSharedMemorySize,
                         GEMM_SMEM);

    const int TPB = 256;
    const int node_grid = (N * D_ + TPB - 1) / TPB;
    const int edge_grid = (E * D_ + TPB - 1) / TPB;
    const dim3 g1grid((TWOD_ + BN - 1) / BN, (N + BM - 1) / BM);
    const dim3 g2grid((D_ + BN - 1) / BN,   (N + BM - 1) / BM);
    const int wp1 = (NCP1 * KPAD1 + TPB - 1) / TPB;
    const int wp2 = (NCP2 * KPAD2 + TPB - 1) / TPB;

    k_atom<<<node_grid, TPB>>>(x, atom, eps, N);

    for (int l = 0; l < 5; ++l) {
        k_edge<<<edge_grid, TPB>>>(ei, ea, bond, E, l);
        k_wprep<<<wp1, TPB>>>(W1 + (size_t)l * D_ * TWOD_, pw1h, pw1l,
                              D_, TWOD_, KPAD1, NCP1);
        k_wprep<<<wp2, TPB>>>(W2 + (size_t)l * TWOD_ * D_, pw2h, pw2l,
                              TWOD_, D_, KPAD2, NCP2);
        // h1 = z @ W1 + b1
        k_gemm_mma<<<g1grid, TPB, GEMM_SMEM>>>(pz, pw1h, pw1l,
                                               b1 + l * TWOD_, ph1,
                                               N, D_, KPAD1, TWOD_,
                                               nullptr, nullptr);
        k_stats<<<STAT_BLOCKS, TWOD_>>>(ph1, N, TWOD_);
        k_finalize<<<1, TWOD_>>>(g1 + l * TWOD_, be1 + l * TWOD_, N, TWOD_);
        // z2 = relu(BN1(h1)) @ W2 + b2  (BN+relu fused into A path)
        k_gemm_mma<<<g2grid, TPB, GEMM_SMEM>>>(ph1, pw2h, pw2l,
                                               b2 + l * D_, pz2,
                                               N, TWOD_, KPAD2, D_,
                                               pA, pB);
        k_stats<<<STAT_BLOCKS, D_>>>(pz2, N, D_);
        k_finalize<<<1, D_>>>(gamma + l * D_, beta + l * D_, N, D_);
        if (l < 4)
            k_apply<<<node_grid, TPB>>>(eps, l + 1, 1, N, nullptr);
        else
            k_apply<<<node_grid, TPB>>>(eps, 0, 0, N, out);
    }
}

// round 6
// speedup vs baseline: 1.2271x; 1.1842x over previous
#include <cuda_runtime.h>
#include <cstdint>

// Problem constants: N=50000, E=250000, D=300, L=5
#define D_    300
#define TWOD_ 600
#define NMAX  50000
#define EMAX_ 250000
#define STAT_BLOCKS 200
#define DEG_CAP 64
#define KPAD1 320   // 300 -> 10 chunks of 32
#define KPAD2 608   // 600 -> 19 chunks of 32
#define NCP1  640   // 600 -> 5 tiles of 128 (zero-padded rows)
#define NCP2  384   // 300 -> 3 tiles of 128

// GEMM tiling
#define BM 128
#define BN 128
#define BK 32
#define STR 40                 // smem row stride in floats (32 data + 8 pad)
#define TSZ (128 * STR)
#define AHO 0
#define ALO TSZ
#define BHO (2 * TSZ)
#define BLO (3 * TSZ)
#define BUFSZ (4 * TSZ)
#define GEMM_SMEM (2 * BUFSZ * 4)

// ---- static scratch (no allocations allowed) ----
__device__ float g_h [NMAX * D_];
__device__ float g_z [NMAX * D_];
__device__ float g_h1[NMAX * TWOD_];
__device__ float g_z2[NMAX * D_];
__device__ float g_ps[STAT_BLOCKS * TWOD_];
__device__ float g_pq[STAT_BLOCKS * TWOD_];
__device__ float g_bnA[TWOD_];
__device__ float g_bnB[TWOD_];
__device__ int   g_fill[NMAX];            // per-node in-degree counter
__device__ int   g_eid [NMAX * DEG_CAP];  // bucketed incoming-edge ids
// pre-transposed + tf32-split + k-permuted + zero-padded weights
__device__ float g_w1h[NCP1 * KPAD1];
__device__ float g_w1l[NCP1 * KPAD1];
__device__ float g_w2h[NCP2 * KPAD2];
__device__ float g_w2l[NCP2 * KPAD2];

// ============================================================
// helpers (baseline PTX only — safe under virtual arch compute_103)
// ============================================================
__device__ __forceinline__ uint32_t smem_u32(const void* p) {
    uint32_t a;
    asm("{ .reg .u64 t; cvta.to.shared.u64 t, %1; cvt.u32.u64 %0, t; }"
        : "=r"(a) : "l"(p));
    return a;
}
__device__ __forceinline__ void cp16(uint32_t dst, const void* src) {
    asm volatile("cp.async.cg.shared.global [%0], [%1], 16;"
                 :: "r"(dst), "l"(src) : "memory");
}
__device__ __forceinline__ void cp_commit() {
    asm volatile("cp.async.commit_group;" ::: "memory");
}
__device__ __forceinline__ void cp_wait0() {
    asm volatile("cp.async.wait_group 0;" ::: "memory");
}
__device__ __forceinline__ void tf32s(float a, uint32_t& hb, uint32_t& lb) {
    asm("cvt.rna.tf32.f32 %0, %1;" : "=r"(hb) : "f"(a));
    float d = a - __uint_as_float(hb);
    asm("cvt.rna.tf32.f32 %0, %1;" : "=r"(lb) : "f"(d));
}
__device__ __forceinline__ void mma8(float* c,
                                     uint32_t a0, uint32_t a1, uint32_t a2, uint32_t a3,
                                     uint32_t b0, uint32_t b1) {
    asm volatile(
        "mma.sync.aligned.m16n8k8.row.col.f32.tf32.tf32.f32 "
        "{%0,%1,%2,%3}, {%4,%5,%6,%7}, {%8,%9}, {%0,%1,%2,%3};"
        : "+f"(c[0]), "+f"(c[1]), "+f"(c[2]), "+f"(c[3])
        : "r"(a0), "r"(a1), "r"(a2), "r"(a3), "r"(b0), "r"(b1));
}

// ============================================================
// Atom encoder: h = sum of embeddings; also zero the bucket counters
// ============================================================
__global__ void k_atom(const int* __restrict__ x, const float* __restrict__ emb, int n)
{
    int idx = blockIdx.x * blockDim.x + threadIdx.x;
    if (idx < n) g_fill[idx] = 0;
    if (idx >= n * D_) return;
    int node = idx / D_;
    int d    = idx - node * D_;
    const int* xr = x + node * 9;
    float s = 0.f;
#pragma unroll
    for (int i = 0; i < 9; i++)
        s += emb[(i * 128 + xr[i]) * D_ + d];
    g_h[idx] = s;
}

// ============================================================
// Build inverted index: bucket incoming edge ids per dst node
// ============================================================
__global__ void k_scatter(const int* __restrict__ ei, int E_)
{
    int e = blockIdx.x * blockDim.x + threadIdx.x;
    if (e >= E_) return;
    int dst = ei[E_ + e];
    int p = atomicAdd(&g_fill[dst], 1);
    if (p < DEG_CAP) g_eid[dst * DEG_CAP + p] = e;
}

// ============================================================
// Aggregation (atomic-free): warp per dst node, float4 lanes over D.
// z[v] = (1+eps_l)*h[v] + sum_{e->v} relu(h[src] + bond_sum(e))
// ============================================================
__device__ __forceinline__ float4 msg4(float4 h, float4 a, float4 b, float4 c) {
    float4 m;
    m.x = fmaxf(h.x + a.x + b.x + c.x, 0.f);
    m.y = fmaxf(h.y + a.y + b.y + c.y, 0.f);
    m.z = fmaxf(h.z + a.z + b.z + c.z, 0.f);
    m.w = fmaxf(h.w + a.w + b.w + c.w, 0.f);
    return m;
}
__global__ void k_aggregate(const int* __restrict__ ei, const int* __restrict__ ea,
                            const float* __restrict__ bond,
                            const float* __restrict__ eps, int n, int layer)
{
    int w    = (blockIdx.x * blockDim.x + threadIdx.x) >> 5;
    int lane = threadIdx.x & 31;
    if (w >= n) return;
    int deg = g_fill[w];
    if (deg > DEG_CAP) deg = DEG_CAP;

    const float4* h4 = (const float4*)g_h;
    const float4* bl = (const float4*)(bond + (size_t)layer * 3 * 16 * D_);
    const int l2 = lane + 32, l3 = lane + 64;
    float4 a0 = make_float4(0.f, 0.f, 0.f, 0.f), a1 = a0, a2 = a0;

    const int* bucket = g_eid + (size_t)w * DEG_CAP;
    for (int p = 0; p < deg; ++p) {
        int eid = bucket[p];
        int src = ei[eid];
        int t3  = eid * 3;
        int c0 = ea[t3], c1 = ea[t3 + 1], c2 = ea[t3 + 2];
        const float4* hr = h4 + (size_t)src * 75;
        const float4* r0 = bl + c0 * 75;
        const float4* r1 = bl + (16 + c1) * 75;
        const float4* r2 = bl + (32 + c2) * 75;
        float4 m;
        m = msg4(hr[lane], r0[lane], r1[lane], r2[lane]);
        a0.x += m.x; a0.y += m.y; a0.z += m.z; a0.w += m.w;
        m = msg4(hr[l2], r0[l2], r1[l2], r2[l2]);
        a1.x += m.x; a1.y += m.y; a1.z += m.z; a1.w += m.w;
        if (l3 < 75) {
            m = msg4(hr[l3], r0[l3], r1[l3], r2[l3]);
            a2.x += m.x; a2.y += m.y; a2.z += m.z; a2.w += m.w;
        }
    }
    float ep = 1.f + eps[layer];
    const float4* hv = h4 + (size_t)w * 75;
    float4* zv = (float4*)g_z + (size_t)w * 75;
    float4 h, o;
    h = hv[lane];
    o.x = fmaf(ep, h.x, a0.x); o.y = fmaf(ep, h.y, a0.y);
    o.z = fmaf(ep, h.z, a0.z); o.w = fmaf(ep, h.w, a0.w);
    zv[lane] = o;
    h = hv[l2];
    o.x = fmaf(ep, h.x, a1.x); o.y = fmaf(ep, h.y, a1.y);
    o.z = fmaf(ep, h.z, a1.z); o.w = fmaf(ep, h.w, a1.w);
    zv[l2] = o;
    if (l3 < 75) {
        h = hv[l3];
        o.x = fmaf(ep, h.x, a2.x); o.y = fmaf(ep, h.y, a2.y);
        o.z = fmaf(ep, h.z, a2.z); o.w = fmaf(ep, h.w, a2.w);
        zv[l3] = o;
    }
}

// ============================================================
// Weight prep (transpose + tf32 split + k-permute + pad)
// ============================================================
__global__ void k_wprep(const float* __restrict__ W, float* __restrict__ Wh,
                        float* __restrict__ Wl, int K, int NC, int Kpad, int NCpad)
{
    int idx = blockIdx.x * blockDim.x + threadIdx.x;
    if (idx >= NCpad * Kpad) return;
    int n  = idx / Kpad;
    int kp = idx - n * Kpad;
    float v = (kp < K && n < NC) ? W[kp * NC + n] : 0.f;
    uint32_t hb, lb;
    tf32s(v, hb, lb);
    int kperm = (kp & ~7) | ((kp & 3) << 1) | ((kp & 7) >> 2);
    Wh[n * Kpad + kperm] = __uint_as_float(hb);
    Wl[n * Kpad + kperm] = __uint_as_float(lb);
}

// ============================================================
// 3xTF32 mma.sync GEMM (unchanged from R5)
// ============================================================
__global__ void __launch_bounds__(256, 1) k_gemm_mma(
    const float* __restrict__ A,
    const float* __restrict__ Bh, const float* __restrict__ Bl,
    const float* __restrict__ bias, float* __restrict__ C,
    int M, int K, int Kpad, int NC,
    const float* __restrict__ sA, const float* __restrict__ sB)
{
    extern __shared__ float sm[];
    const int tid = threadIdx.x;
    const int wid = tid >> 5, lid = tid & 31;
    const int g = lid >> 2, t4 = lid & 3;
    const int wm = wid >> 2, wn = wid & 3;
    const int bm = blockIdx.y * BM, bn = blockIdx.x * BN;
    const int nch = Kpad / BK;
    const bool fuse = (sA != nullptr);

    const int lr = tid >> 1;
    const int lh = tid & 1;
    const bool aOk = (bm + lr) < M;
    const float* Ap = A + (size_t)(bm + lr) * K;
    const size_t bRow = (size_t)(bn + lr) * Kpad + lh * 16;
    const uint32_t sm32 = smem_u32(sm);
    const uint32_t cpBH = sm32 + (uint32_t)((BHO + lr * STR + lh * 16) * 4);
    const uint32_t cpBL = sm32 + (uint32_t)((BLO + lr * STR + lh * 16) * 4);

    float acc[4][4][4];
#pragma unroll
    for (int i = 0; i < 4; i++)
#pragma unroll
        for (int j = 0; j < 4; j++)
#pragma unroll
            for (int k = 0; k < 4; k++) acc[i][j][k] = 0.f;

    float4 av[4];

#define LOAD_A(K0)                                                        \
    {                                                                     \
        const int kkb = (K0) + lh * 16;                                   \
        _Pragma("unroll")                                                 \
        for (int q = 0; q < 4; ++q) {                                     \
            int ka = kkb + 4 * q;                                         \
            float4 v = make_float4(0.f, 0.f, 0.f, 0.f);                   \
            if (aOk && ka < K) {                                          \
                v = *(const float4*)(Ap + ka);                            \
                if (fuse) {                                               \
                    float4 s4 = *(const float4*)(sA + ka);                \
                    float4 h4 = *(const float4*)(sB + ka);                \
                    v.x = fmaxf(fmaf(v.x, s4.x, h4.x), 0.f);              \
                    v.y = fmaxf(fmaf(v.y, s4.y, h4.y), 0.f);              \
                    v.z = fmaxf(fmaf(v.z, s4.z, h4.z), 0.f);              \
                    v.w = fmaxf(fmaf(v.w, s4.w, h4.w), 0.f);              \
                }                                                         \
            }                                                             \
            av[q] = v;                                                    \
        }                                                                 \
    }

#define CP_B(BUFO, K0)                                                    \
    {                                                                     \
        const uint32_t bo4 = (uint32_t)((BUFO) * 4);                      \
        const float* sh = Bh + bRow + (K0);                               \
        const float* sl = Bl + bRow + (K0);                               \
        _Pragma("unroll")                                                 \
        for (int u = 0; u < 4; ++u) {                                     \
            cp16(cpBH + bo4 + u * 16, sh + u * 4);                        \
            cp16(cpBL + bo4 + u * 16, sl + u * 4);                        \
        }                                                                 \
    }

#define STORE_A(BUFO)                                                     \
    {                                                                     \
        float f[16];                                                      \
        *(float4*)&f[0]  = av[0];                                         \
        *(float4*)&f[4]  = av[1];                                         \
        *(float4*)&f[8]  = av[2];                                         \
        *(float4*)&f[12] = av[3];                                         \
        uint32_t hb[16], lb[16];                                          \
        _Pragma("unroll")                                                 \
        for (int i = 0; i < 16; ++i) tf32s(f[i], hb[i], lb[i]);           \
        uint4* dH = (uint4*)(sm + (BUFO) + AHO + lr * STR + lh * 16);     \
        uint4* dL = (uint4*)(sm + (BUFO) + ALO + lr * STR + lh * 16);     \
        dH[0] = make_uint4(hb[0], hb[4],  hb[1], hb[5]);                  \
        dH[1] = make_uint4(hb[2], hb[6],  hb[3], hb[7]);                  \
        dH[2] = make_uint4(hb[8], hb[12], hb[9], hb[13]);                 \
        dH[3] = make_uint4(hb[10],hb[14], hb[11],hb[15]);                 \
        dL[0] = make_uint4(lb[0], lb[4],  lb[1], lb[5]);                  \
        dL[1] = make_uint4(lb[2], lb[6],  lb[3], lb[7]);                  \
        dL[2] = make_uint4(lb[8], lb[12], lb[9], lb[13]);                 \
        dL[3] = make_uint4(lb[10],lb[14], lb[11],lb[15]);                 \
    }

    LOAD_A(0);
    CP_B(0, 0);
    cp_commit();
    STORE_A(0);
    cp_wait0();
    __syncthreads();

    for (int c = 0; c < nch; ++c) {
        const int bufc = (c & 1) * BUFSZ;
        const int bufn = ((c + 1) & 1) * BUFSZ;
        if (c + 1 < nch) {
            LOAD_A((c + 1) * BK);
            CP_B(bufn, (c + 1) * BK);
            cp_commit();
        }
        {
            const float* aH = sm + bufc + AHO;
            const float* aL = sm + bufc + ALO;
            const float* bH = sm + bufc + BHO;
            const float* bL = sm + bufc + BLO;
#pragma unroll
            for (int j = 0; j < 4; ++j) {
                const int ko = j * 8 + 2 * t4;
                uint2 fbh[4], fbl[4];
#pragma unroll
                for (int nt = 0; nt < 4; ++nt) {
                    const int n = wn * 32 + nt * 8 + g;
                    fbh[nt] = *(const uint2*)(bH + n * STR + ko);
                    fbl[nt] = *(const uint2*)(bL + n * STR + ko);
                }
#pragma unroll
                for (int mt = 0; mt < 4; ++mt) {
                    const int r0 = wm * 64 + mt * 16 + g;
                    uint2 h0 = *(const uint2*)(aH + r0 * STR + ko);
                    uint2 h1 = *(const uint2*)(aH + (r0 + 8) * STR + ko);
                    uint2 l0 = *(const uint2*)(aL + r0 * STR + ko);
                    uint2 l1 = *(const uint2*)(aL + (r0 + 8) * STR + ko);
#pragma unroll
                    for (int nt = 0; nt < 4; ++nt) {
                        mma8(acc[mt][nt], h0.x, h1.x, h0.y, h1.y, fbh[nt].x, fbh[nt].y);
                        mma8(acc[mt][nt], h0.x, h1.x, h0.y, h1.y, fbl[nt].x, fbl[nt].y);
                        mma8(acc[mt][nt], l0.x, l1.x, l0.y, l1.y, fbh[nt].x, fbh[nt].y);
                    }
                }
            }
        }
        if (c + 1 < nch) {
            STORE_A(bufn);
            cp_wait0();
        }
        __syncthreads();
    }

#pragma unroll
    for (int mt = 0; mt < 4; ++mt) {
        const int r0g = bm + wm * 64 + mt * 16 + g;
#pragma unroll
        for (int nt = 0; nt < 4; ++nt) {
            const int col = bn + wn * 32 + nt * 8 + 2 * t4;
            if (col < NC) {
                const float b0 = bias[col];
                const float b1 = bias[col + 1];
                const float* a4 = acc[mt][nt];
                if (r0g < M) {
                    float2 v = make_float2(a4[0] + b0, a4[1] + b1);
                    *(float2*)(C + (size_t)r0g * NC + col) = v;
                }
                if (r0g + 8 < M) {
                    float2 v = make_float2(a4[2] + b0, a4[3] + b1);
                    *(float2*)(C + (size_t)(r0g + 8) * NC + col) = v;
                }
            }
        }
    }
#undef LOAD_A
#undef CP_B
#undef STORE_A
}

// ============================================================
// Column stats + BN finalize + apply
// ============================================================
__global__ void k_stats(const float* __restrict__ X, int M, int C)
{
    int c = threadIdx.x;
    int rows = (M + gridDim.x - 1) / gridDim.x;
    int r0 = blockIdx.x * rows;
    int r1 = min(M, r0 + rows);
    float s = 0.f, q = 0.f;
    for (int r = r0; r < r1; ++r) {
        float v = X[(size_t)r * C + c];
        s += v;
        q += v * v;
    }
    g_ps[blockIdx.x * C + c] = s;
    g_pq[blockIdx.x * C + c] = q;
}

__global__ void k_finalize(const float* __restrict__ g, const float* __restrict__ b,
                           int M, int C)
{
    int c = threadIdx.x;
    float s = 0.f, q = 0.f;
#pragma unroll 4
    for (int i = 0; i < STAT_BLOCKS; i++) {
        s += g_ps[i * C + c];
        q += g_pq[i * C + c];
    }
    float mean = s / (float)M;
    float var  = q / (float)M - mean * mean;
    float a = g[c] * rsqrtf(var + 1e-5f);
    g_bnA[c] = a;
    g_bnB[c] = fmaf(-mean, a, b[c]);
}

__global__ void k_apply(int do_relu, int n, float* __restrict__ out)
{
    int idx = blockIdx.x * blockDim.x + threadIdx.x;
    if (idx >= n * D_) return;
    int c = idx % D_;
    float v = fmaf(g_z2[idx], g_bnA[c], g_bnB[c]);
    if (do_relu) v = fmaxf(v, 0.f);
    if (out) out[idx] = v;
    else     g_h[idx] = v;
}

// ============================================================
// Launch
// ============================================================
extern "C" void kernel_launch(void* const* d_in, const int* in_sizes, int n_in,
                              void* d_out, int out_size)
{
    const int*   x     = (const int*)  d_in[0];
    const int*   ei    = (const int*)  d_in[1];
    const int*   ea    = (const int*)  d_in[2];
    const float* atom  = (const float*)d_in[3];
    const float* bond  = (const float*)d_in[4];
    const float* eps   = (const float*)d_in[5];
    const float* W1    = (const float*)d_in[6];
    const float* b1    = (const float*)d_in[7];
    const float* g1    = (const float*)d_in[8];
    const float* be1   = (const float*)d_in[9];
    const float* W2    = (const float*)d_in[10];
    const float* b2    = (const float*)d_in[11];
    const float* gamma = (const float*)d_in[12];
    const float* beta  = (const float*)d_in[13];
    float* out = (float*)d_out;

    const int N = in_sizes[0] / 9;
    const int E = in_sizes[1] / 2;

    float *ph1, *pz, *pz2, *pA, *pB;
    float *pw1h, *pw1l, *pw2h, *pw2l;
    cudaGetSymbolAddress((void**)&pz,   g_z);
    cudaGetSymbolAddress((void**)&ph1,  g_h1);
    cudaGetSymbolAddress((void**)&pz2,  g_z2);
    cudaGetSymbolAddress((void**)&pA,   g_bnA);
    cudaGetSymbolAddress((void**)&pB,   g_bnB);
    cudaGetSymbolAddress((void**)&pw1h, g_w1h);
    cudaGetSymbolAddress((void**)&pw1l, g_w1l);
    cudaGetSymbolAddress((void**)&pw2h, g_w2h);
    cudaGetSymbolAddress((void**)&pw2l, g_w2l);

    cudaFuncSetAttribute(k_gemm_mma, cudaFuncAttributeMaxDynamicSharedMemorySize,
                         GEMM_SMEM);

    const int TPB = 256;
    const int node_grid = (N * D_ + TPB - 1) / TPB;
    const int agg_grid  = (N + 7) / 8;                 // warp per node
    const dim3 g1grid((TWOD_ + BN - 1) / BN, (N + BM - 1) / BM);
    const dim3 g2grid((D_ + BN - 1) / BN,   (N + BM - 1) / BM);
    const int wp1 = (NCP1 * KPAD1 + TPB - 1) / TPB;
    const int wp2 = (NCP2 * KPAD2 + TPB - 1) / TPB;

    // 1: h = AtomEncoder(x); zero bucket counters
    k_atom<<<node_grid, TPB>>>(x, atom, N);
    // 2: W1(l=0) prep (independent — ordered here so aggregate lands in the
    //    ncu-profiled launch slot)
    k_wprep<<<wp1, TPB>>>(W1, pw1h, pw1l, D_, TWOD_, KPAD1, NCP1);
    // 3: bucket incoming edges per dst
    k_scatter<<<(E + TPB - 1) / TPB, TPB>>>(ei, E);

    for (int l = 0; l < 5; ++l) {
        if (l > 0)
            k_wprep<<<wp1, TPB>>>(W1 + (size_t)l * D_ * TWOD_, pw1h, pw1l,
                                  D_, TWOD_, KPAD1, NCP1);
        // 4 (l=0): atomic-free aggregation: z = (1+eps)h + segment_sum(relu(h[src]+e))
        k_aggregate<<<agg_grid, TPB>>>(ei, ea, bond, eps, N, l);
        // h1 = z @ W1 + b1
        k_gemm_mma<<<g1grid, TPB, GEMM_SMEM>>>(pz, pw1h, pw1l,
                                               b1 + l * TWOD_, ph1,
                                               N, D_, KPAD1, TWOD_,
                                               nullptr, nullptr);
        k_stats<<<STAT_BLOCKS, TWOD_>>>(ph1, N, TWOD_);
        k_finalize<<<1, TWOD_>>>(g1 + l * TWOD_, be1 + l * TWOD_, N, TWOD_);
        k_wprep<<<wp2, TPB>>>(W2 + (size_t)l * TWOD_ * D_, pw2h, pw2l,
                              TWOD_, D_, KPAD2, NCP2);
        // z2 = relu(BN1(h1)) @ W2 + b2  (BN+relu fused into A path)
        k_gemm_mma<<<g2grid, TPB, GEMM_SMEM>>>(ph1, pw2h, pw2l,
                                               b2 + l * D_, pz2,
                                               N, TWOD_, KPAD2, D_,
                                               pA, pB);
        k_stats<<<STAT_BLOCKS, D_>>>(pz2, N, D_);
        k_finalize<<<1, D_>>>(gamma + l * D_, beta + l * D_, N, D_);
        if (l < 4)
            k_apply<<<node_grid, TPB>>>(1, N, nullptr);
        else
            k_apply<<<node_grid, TPB>>>(0, N, out);
    }
}

// round 8
// speedup vs baseline: 1.7974x; 1.4647x over previous
#include <cuda_runtime.h>
#include <cuda_bf16.h>
#include <cstdint>

// Problem constants: N=50000, E=250000, D=300, L=5
#define D_    300
#define TWOD_ 600
#define NMAX  50000
#define DEG_CAP 64
#define KPAD1 320   // 300 -> 10 chunks of 32
#define KPAD2 608   // 600 -> 19 chunks of 32
#define NCP1  640   // 600 -> 5 tiles of 128 (zero-padded rows)
#define NCP2  384   // 300 -> 3 tiles of 128

// GEMM tiling (bf16 pairs: one uint32 = 2 bf16 along k)
#define BM 128
#define BN 128
#define BK 32                  // k per chunk (16 uint32 pairs)
#define STRU 24                // smem row stride in uint32 (16 data + 8 pad)
#define TSZU (128 * STRU)      // 3072 uint32 per tile
#define AHO_U 0
#define ALO_U TSZU
#define BHO_U (2 * TSZU)
#define BLO_U (3 * TSZU)
#define BUFSZ_U (4 * TSZU)     // 12288 uint32 per stage
#define GEMM_SMEM (2 * BUFSZ_U * 4)   // 98304 bytes

// ---- static scratch (no allocations allowed) ----
__device__ float g_h [NMAX * D_];
__device__ float g_z [NMAX * D_];
__device__ float g_h1[NMAX * TWOD_];
__device__ float g_z2[NMAX * D_];
__device__ float g_cs[TWOD_];            // fused column sums
__device__ float g_cq[TWOD_];            // fused column sumsq
__device__ float g_bnA[TWOD_];
__device__ float g_bnB[TWOD_];
__device__ int   g_fill[NMAX];
__device__ int   g_eid [NMAX * DEG_CAP];
// pre-transposed + bf16-split + pair-permuted + padded weights (packed bf16x2)
__device__ uint32_t g_w1h[NCP1 * KPAD1 / 2];
__device__ uint32_t g_w1l[NCP1 * KPAD1 / 2];
__device__ uint32_t g_w2h[NCP2 * KPAD2 / 2];
__device__ uint32_t g_w2l[NCP2 * KPAD2 / 2];

// ============================================================
// helpers (baseline PTX only — safe under virtual arch compute_103)
// ============================================================
__device__ __forceinline__ uint32_t smem_u32(const void* p) {
    uint32_t a;
    asm("{ .reg .u64 t; cvta.to.shared.u64 t, %1; cvt.u32.u64 %0, t; }"
        : "=r"(a) : "l"(p));
    return a;
}
__device__ __forceinline__ void cp16(uint32_t dst, const void* src) {
    asm volatile("cp.async.cg.shared.global [%0], [%1], 16;"
                 :: "r"(dst), "l"(src) : "memory");
}
__device__ __forceinline__ void cp_commit() {
    asm volatile("cp.async.commit_group;" ::: "memory");
}
__device__ __forceinline__ void cp_wait0() {
    asm volatile("cp.async.wait_group 0;" ::: "memory");
}
// bf16 residual split: v = hi + lo (both bf16)
__device__ __forceinline__ void bf16s(float v, uint16_t& h, uint16_t& l) {
    __nv_bfloat16 hb = __float2bfloat16(v);
    float r = v - __bfloat162float(hb);
    __nv_bfloat16 lb = __float2bfloat16(r);
    h = __bfloat16_as_ushort(hb);
    l = __bfloat16_as_ushort(lb);
}
// m16n8k16 bf16 MMA (row.col), fp32 accumulate
__device__ __forceinline__ void mma16(float* c,
                                      uint32_t a0, uint32_t a1, uint32_t a2, uint32_t a3,
                                      uint32_t b0, uint32_t b1) {
    asm volatile(
        "mma.sync.aligned.m16n8k16.row.col.f32.bf16.bf16.f32 "
        "{%0,%1,%2,%3}, {%4,%5,%6,%7}, {%8,%9}, {%0,%1,%2,%3};"
        : "+f"(c[0]), "+f"(c[1]), "+f"(c[2]), "+f"(c[3])
        : "r"(a0), "r"(a1), "r"(a2), "r"(a3), "r"(b0), "r"(b1));
}

// ============================================================
// Atom encoder: h = sum of embeddings; zero bucket counters
// ============================================================
__global__ void k_atom(const int* __restrict__ x, const float* __restrict__ emb, int n)
{
    int idx = blockIdx.x * blockDim.x + threadIdx.x;
    if (idx < n) g_fill[idx] = 0;
    if (idx >= n * D_) return;
    int node = idx / D_;
    int d    = idx - node * D_;
    const int* xr = x + node * 9;
    float s = 0.f;
#pragma unroll
    for (int i = 0; i < 9; i++)
        s += emb[(i * 128 + xr[i]) * D_ + d];
    g_h[idx] = s;
}

// ============================================================
// Build inverted index
// ============================================================
__global__ void k_scatter(const int* __restrict__ ei, int E_)
{
    int e = blockIdx.x * blockDim.x + threadIdx.x;
    if (e >= E_) return;
    int dst = ei[E_ + e];
    int p = atomicAdd(&g_fill[dst], 1);
    if (p < DEG_CAP) g_eid[dst * DEG_CAP + p] = e;
}

// ============================================================
// Aggregation (atomic-free): warp per dst node, float4 lanes over D
// ============================================================
__device__ __forceinline__ float4 msg4(float4 h, float4 a, float4 b, float4 c) {
    float4 m;
    m.x = fmaxf(h.x + a.x + b.x + c.x, 0.f);
    m.y = fmaxf(h.y + a.y + b.y + c.y, 0.f);
    m.z = fmaxf(h.z + a.z + b.z + c.z, 0.f);
    m.w = fmaxf(h.w + a.w + b.w + c.w, 0.f);
    return m;
}
__global__ void k_aggregate(const int* __restrict__ ei, const int* __restrict__ ea,
                            const float* __restrict__ bond,
                            const float* __restrict__ eps, int n, int layer)
{
    int w    = (blockIdx.x * blockDim.x + threadIdx.x) >> 5;
    int lane = threadIdx.x & 31;
    if (w >= n) return;
    int deg = g_fill[w];
    if (deg > DEG_CAP) deg = DEG_CAP;

    const float4* h4 = (const float4*)g_h;
    const float4* bl = (const float4*)(bond + (size_t)layer * 3 * 16 * D_);
    const int l2 = lane + 32, l3 = lane + 64;
    float4 a0 = make_float4(0.f, 0.f, 0.f, 0.f), a1 = a0, a2 = a0;

    const int* bucket = g_eid + (size_t)w * DEG_CAP;
    for (int p = 0; p < deg; ++p) {
        int eid = bucket[p];
        int src = ei[eid];
        int t3  = eid * 3;
        int c0 = ea[t3], c1 = ea[t3 + 1], c2 = ea[t3 + 2];
        const float4* hr = h4 + (size_t)src * 75;
        const float4* r0 = bl + c0 * 75;
        const float4* r1 = bl + (16 + c1) * 75;
        const float4* r2 = bl + (32 + c2) * 75;
        float4 m;
        m = msg4(hr[lane], r0[lane], r1[lane], r2[lane]);
        a0.x += m.x; a0.y += m.y; a0.z += m.z; a0.w += m.w;
        m = msg4(hr[l2], r0[l2], r1[l2], r2[l2]);
        a1.x += m.x; a1.y += m.y; a1.z += m.z; a1.w += m.w;
        if (l3 < 75) {
            m = msg4(hr[l3], r0[l3], r1[l3], r2[l3]);
            a2.x += m.x; a2.y += m.y; a2.z += m.z; a2.w += m.w;
        }
    }
    float ep = 1.f + eps[layer];
    const float4* hv = h4 + (size_t)w * 75;
    float4* zv = (float4*)g_z + (size_t)w * 75;
    float4 h, o;
    h = hv[lane];
    o.x = fmaf(ep, h.x, a0.x); o.y = fmaf(ep, h.y, a0.y);
    o.z = fmaf(ep, h.z, a0.z); o.w = fmaf(ep, h.w, a0.w);
    zv[lane] = o;
    h = hv[l2];
    o.x = fmaf(ep, h.x, a1.x); o.y = fmaf(ep, h.y, a1.y);
    o.z = fmaf(ep, h.z, a1.z); o.w = fmaf(ep, h.w, a1.w);
    zv[l2] = o;
    if (l3 < 75) {
        h = hv[l3];
        o.x = fmaf(ep, h.x, a2.x); o.y = fmaf(ep, h.y, a2.y);
        o.z = fmaf(ep, h.z, a2.z); o.w = fmaf(ep, h.w, a2.w);
        zv[l3] = o;
    }
}

// ============================================================
// Weight prep: transpose + bf16-split + pair-permute + pad; packed bf16x2.
// Also zeroes the fused-stat accumulators.
// pair permutation within each 32k chunk: pos = s*8 + 2*(p&3) + (p>>2)
// ============================================================
__global__ void k_wprep(const float* __restrict__ W, uint32_t* __restrict__ Wh,
                        uint32_t* __restrict__ Wl, int K, int NC, int Kpad, int NCpad)
{
    int idx = blockIdx.x * blockDim.x + threadIdx.x;
    if (idx < TWOD_) { g_cs[idx] = 0.f; g_cq[idx] = 0.f; }
    const int Kp2 = Kpad >> 1;
    if (idx >= NCpad * Kp2) return;
    int n   = idx / Kp2;
    int kp2 = idx - n * Kp2;
    int k0 = 2 * kp2, k1 = k0 + 1;
    float v0 = (k0 < K && n < NC) ? W[k0 * NC + n] : 0.f;
    float v1 = (k1 < K && n < NC) ? W[k1 * NC + n] : 0.f;
    uint16_t h0, l0, h1, l1;
    bf16s(v0, h0, l0);
    bf16s(v1, h1, l1);
    int c  = kp2 >> 4;
    int pp = kp2 & 15;
    int s  = pp >> 3;
    int p  = pp & 7;
    int pos = s * 8 + 2 * (p & 3) + (p >> 2);
    int dsti = n * Kp2 + c * 16 + pos;
    Wh[dsti] = (uint32_t)h0 | ((uint32_t)h1 << 16);
    Wl[dsti] = (uint32_t)l0 | ((uint32_t)l1 << 16);
}

// ============================================================
// 3xBF16 mma.sync GEMM with fused column stats:
//   C = op(A) @ W + bias;  g_cs/g_cq += column sum / sumsq of C (valid rows)
//   op(A) = relu(A*sA + sB) when sA != nullptr (fused BN+relu)
// 128x128x32 tiles, 8 warps (2x4), double-buffered.
// ============================================================
__global__ void __launch_bounds__(256, 1) k_gemm_mma(
    const float* __restrict__ A,
    const uint32_t* __restrict__ Bh, const uint32_t* __restrict__ Bl,
    const float* __restrict__ bias, float* __restrict__ C,
    int M, int K, int Kpad, int NC,
    const float* __restrict__ sA, const float* __restrict__ sB)
{
    extern __shared__ uint32_t smu[];
    const int tid = threadIdx.x;
    const int wid = tid >> 5, lid = tid & 31;
    const int g = lid >> 2, t4 = lid & 3;
    const int wm = wid >> 2, wn = wid & 3;
    const int bm = blockIdx.y * BM, bn = blockIdx.x * BN;
    const int nch = Kpad / BK;
    const int Kp2 = Kpad >> 1;
    const bool fuse = (sA != nullptr);

    const int lr = tid >> 1;          // loader row 0..127
    const int lh = tid & 1;           // loader k-half (16 k = 8 pairs)
    const bool aOk = (bm + lr) < M;
    const float* Ap = A + (size_t)(bm + lr) * K;
    const uint32_t* BhRow = Bh + (size_t)(bn + lr) * Kp2 + lh * 8;
    const uint32_t* BlRow = Bl + (size_t)(bn + lr) * Kp2 + lh * 8;
    const uint32_t sm32 = smem_u32(smu);
    const uint32_t cpBH = sm32 + (uint32_t)((BHO_U + lr * STRU + lh * 8) * 4);
    const uint32_t cpBL = sm32 + (uint32_t)((BLO_U + lr * STRU + lh * 8) * 4);

    float acc[4][4][4];
#pragma unroll
    for (int i = 0; i < 4; i++)
#pragma unroll
        for (int j = 0; j < 4; j++)
#pragma unroll
            for (int k = 0; k < 4; k++) acc[i][j][k] = 0.f;

    float4 av[4];

#define LOAD_A(K0)                                                        \
    {                                                                     \
        const int kkb = (K0) + lh * 16;                                   \
        _Pragma("unroll")                                                 \
        for (int q = 0; q < 4; ++q) {                                     \
            int ka = kkb + 4 * q;                                         \
            float4 v = make_float4(0.f, 0.f, 0.f, 0.f);                   \
            if (aOk && ka < K) {                                          \
                v = *(const float4*)(Ap + ka);                            \
                if (fuse) {                                               \
                    float4 s4 = *(const float4*)(sA + ka);                \
                    float4 h4 = *(const float4*)(sB + ka);                \
                    v.x = fmaxf(fmaf(v.x, s4.x, h4.x), 0.f);              \
                    v.y = fmaxf(fmaf(v.y, s4.y, h4.y), 0.f);              \
                    v.z = fmaxf(fmaf(v.z, s4.z, h4.z), 0.f);              \
                    v.w = fmaxf(fmaf(v.w, s4.w, h4.w), 0.f);              \
                }                                                         \
            }                                                             \
            av[q] = v;                                                    \
        }                                                                 \
    }

#define CP_B(BUFO_U, C0)                                                  \
    {                                                                     \
        const uint32_t bo4 = (uint32_t)((BUFO_U) * 4);                    \
        const uint32_t* sh = BhRow + (C0) * 16;                           \
        const uint32_t* sl = BlRow + (C0) * 16;                           \
        cp16(cpBH + bo4,      sh);                                        \
        cp16(cpBH + bo4 + 16, sh + 4);                                    \
        cp16(cpBL + bo4,      sl);                                        \
        cp16(cpBL + bo4 + 16, sl + 4);                                    \
    }

#define STORE_A(BUFO_U)                                                   \
    {                                                                     \
        float f[16];                                                      \
        *(float4*)&f[0]  = av[0];                                         \
        *(float4*)&f[4]  = av[1];                                         \
        *(float4*)&f[8]  = av[2];                                         \
        *(float4*)&f[12] = av[3];                                         \
        uint32_t hp[8], lp[8];                                            \
        _Pragma("unroll")                                                 \
        for (int q = 0; q < 8; ++q) {                                     \
            uint16_t h0, l0, h1, l1;                                      \
            bf16s(f[2 * q],     h0, l0);                                  \
            bf16s(f[2 * q + 1], h1, l1);                                  \
            hp[q] = (uint32_t)h0 | ((uint32_t)h1 << 16);                  \
            lp[q] = (uint32_t)l0 | ((uint32_t)l1 << 16);                  \
        }                                                                 \
        uint4* dH = (uint4*)(smu + (BUFO_U) + AHO_U + lr * STRU + lh * 8);\
        uint4* dL = (uint4*)(smu + (BUFO_U) + ALO_U + lr * STRU + lh * 8);\
        dH[0] = make_uint4(hp[0], hp[4], hp[1], hp[5]);                   \
        dH[1] = make_uint4(hp[2], hp[6], hp[3], hp[7]);                   \
        dL[0] = make_uint4(lp[0], lp[4], lp[1], lp[5]);                   \
        dL[1] = make_uint4(lp[2], lp[6], lp[3], lp[7]);                   \
    }

    LOAD_A(0);
    CP_B(0, 0);
    cp_commit();
    STORE_A(0);
    cp_wait0();
    __syncthreads();

    for (int c = 0; c < nch; ++c) {
        const int bufc = (c & 1) * BUFSZ_U;
        const int bufn = ((c + 1) & 1) * BUFSZ_U;
        if (c + 1 < nch) {
            LOAD_A((c + 1) * BK);
            CP_B(bufn, c + 1);
            cp_commit();
        }
        {
            const uint32_t* aH = smu + bufc + AHO_U;
            const uint32_t* aL = smu + bufc + ALO_U;
            const uint32_t* bH = smu + bufc + BHO_U;
            const uint32_t* bL = smu + bufc + BLO_U;
#pragma unroll
            for (int s = 0; s < 2; ++s) {
                const int ko = s * 8 + 2 * t4;
                uint2 fbh[4], fbl[4];
#pragma unroll
                for (int nt = 0; nt < 4; ++nt) {
                    const int n = wn * 32 + nt * 8 + g;
                    fbh[nt] = *(const uint2*)(bH + n * STRU + ko);
                    fbl[nt] = *(const uint2*)(bL + n * STRU + ko);
                }
#pragma unroll
                for (int mt = 0; mt < 4; ++mt) {
                    const int r0 = wm * 64 + mt * 16 + g;
                    uint2 h0 = *(const uint2*)(aH + r0 * STRU + ko);
                    uint2 h1 = *(const uint2*)(aH + (r0 + 8) * STRU + ko);
                    uint2 l0 = *(const uint2*)(aL + r0 * STRU + ko);
                    uint2 l1 = *(const uint2*)(aL + (r0 + 8) * STRU + ko);
#pragma unroll
                    for (int nt = 0; nt < 4; ++nt) {
                        mma16(acc[mt][nt], h0.x, h1.x, h0.y, h1.y, fbh[nt].x, fbh[nt].y);
                        mma16(acc[mt][nt], h0.x, h1.x, h0.y, h1.y, fbl[nt].x, fbl[nt].y);
                        mma16(acc[mt][nt], l0.x, l1.x, l0.y, l1.y, fbh[nt].x, fbh[nt].y);
                    }
                }
            }
        }
        if (c + 1 < nch) {
            STORE_A(bufn);
            cp_wait0();
        }
        __syncthreads();
    }

    // ---- epilogue: +bias, stores, fused column stats ----
#pragma unroll
    for (int nt = 0; nt < 4; ++nt) {
        const int col = bn + wn * 32 + nt * 8 + 2 * t4;   // uniform across g
        const bool cok = col < NC;
        const float b0 = cok ? bias[col]     : 0.f;
        const float b1 = cok ? bias[col + 1] : 0.f;
        float s0 = 0.f, s1 = 0.f, q0 = 0.f, q1 = 0.f;
#pragma unroll
        for (int mt = 0; mt < 4; ++mt) {
            const int r0g = bm + wm * 64 + mt * 16 + g;
            const float* a4 = acc[mt][nt];
            if (cok && r0g < M) {
                float v0 = a4[0] + b0, v1 = a4[1] + b1;
                *(float2*)(C + (size_t)r0g * NC + col) = make_float2(v0, v1);
                s0 += v0; q0 += v0 * v0;
                s1 += v1; q1 += v1 * v1;
            }
            if (cok && r0g + 8 < M) {
                float v2 = a4[2] + b0, v3 = a4[3] + b1;
                *(float2*)(C + (size_t)(r0g + 8) * NC + col) = make_float2(v2, v3);
                s0 += v2; q0 += v2 * v2;
                s1 += v3; q1 += v3 * v3;
            }
        }
        // reduce over g (lanes differing in bits 2..4); all 32 lanes participate
#pragma unroll
        for (int m = 4; m <= 16; m <<= 1) {
            s0 += __shfl_xor_sync(0xffffffffu, s0, m);
            s1 += __shfl_xor_sync(0xffffffffu, s1, m);
            q0 += __shfl_xor_sync(0xffffffffu, q0, m);
            q1 += __shfl_xor_sync(0xffffffffu, q1, m);
        }
        if (cok && g == 0) {
            atomicAdd(&g_cs[col],     s0);
            atomicAdd(&g_cq[col],     q0);
            atomicAdd(&g_cs[col + 1], s1);
            atomicAdd(&g_cq[col + 1], q1);
        }
    }
#undef LOAD_A
#undef CP_B
#undef STORE_A
}

// ============================================================
// BN finalize (reads fused stats) + apply
// ============================================================
__global__ void k_finalize(const float* __restrict__ g, const float* __restrict__ b,
                           int M, int C)
{
    int c = threadIdx.x;
    float mean = g_cs[c] / (float)M;
    float var  = g_cq[c] / (float)M - mean * mean;
    float a = g[c] * rsqrtf(var + 1e-5f);
    g_bnA[c] = a;
    g_bnB[c] = fmaf(-mean, a, b[c]);
}

__global__ void k_apply(int do_relu, int n, float* __restrict__ out)
{
    int idx = blockIdx.x * blockDim.x + threadIdx.x;
    if (idx >= n * D_) return;
    int c = idx % D_;
    float v = fmaf(g_z2[idx], g_bnA[c], g_bnB[c]);
    if (do_relu) v = fmaxf(v, 0.f);
    if (out) out[idx] = v;
    else     g_h[idx] = v;
}

// ============================================================
// Launch
// ============================================================
extern "C" void kernel_launch(void* const* d_in, const int* in_sizes, int n_in,
                              void* d_out, int out_size)
{
    const int*   x     = (const int*)  d_in[0];
    const int*   ei    = (const int*)  d_in[1];
    const int*   ea    = (const int*)  d_in[2];
    const float* atom  = (const float*)d_in[3];
    const float* bond  = (const float*)d_in[4];
    const float* eps   = (const float*)d_in[5];
    const float* W1    = (const float*)d_in[6];
    const float* b1    = (const float*)d_in[7];
    const float* g1    = (const float*)d_in[8];
    const float* be1   = (const float*)d_in[9];
    const float* W2    = (const float*)d_in[10];
    const float* b2    = (const float*)d_in[11];
    const float* gamma = (const float*)d_in[12];
    const float* beta  = (const float*)d_in[13];
    float* out = (float*)d_out;

    const int N = in_sizes[0] / 9;
    const int E = in_sizes[1] / 2;

    float *ph1, *pz, *pz2, *pA, *pB;
    uint32_t *pw1h, *pw1l, *pw2h, *pw2l;
    cudaGetSymbolAddress((void**)&pz,   g_z);
    cudaGetSymbolAddress((void**)&ph1,  g_h1);
    cudaGetSymbolAddress((void**)&pz2,  g_z2);
    cudaGetSymbolAddress((void**)&pA,   g_bnA);
    cudaGetSymbolAddress((void**)&pB,   g_bnB);
    cudaGetSymbolAddress((void**)&pw1h, g_w1h);
    cudaGetSymbolAddress((void**)&pw1l, g_w1l);
    cudaGetSymbolAddress((void**)&pw2h, g_w2h);
    cudaGetSymbolAddress((void**)&pw2l, g_w2l);

    cudaFuncSetAttribute(k_gemm_mma, cudaFuncAttributeMaxDynamicSharedMemorySize,
                         GEMM_SMEM);

    const int TPB = 256;
    const int node_grid = (N * D_ + TPB - 1) / TPB;
    const int agg_grid  = (N + 7) / 8;
    const dim3 g1grid(NCP1 / BN, (N + BM - 1) / BM);
    const dim3 g2grid(NCP2 / BN, (N + BM - 1) / BM);
    const int wp1 = (NCP1 * KPAD1 / 2 + TPB - 1) / TPB;
    const int wp2 = (NCP2 * KPAD2 / 2 + TPB - 1) / TPB;

    k_atom<<<node_grid, TPB>>>(x, atom, N);
    k_wprep<<<wp1, TPB>>>(W1, pw1h, pw1l, D_, TWOD_, KPAD1, NCP1);
    k_scatter<<<(E + TPB - 1) / TPB, TPB>>>(ei, E);

    for (int l = 0; l < 5; ++l) {
        if (l > 0)
            k_wprep<<<wp1, TPB>>>(W1 + (size_t)l * D_ * TWOD_, pw1h, pw1l,
                                  D_, TWOD_, KPAD1, NCP1);
        k_aggregate<<<agg_grid, TPB>>>(ei, ea, bond, eps, N, l);
        // h1 = z @ W1 + b1   (+ fused BN1 stats)
        k_gemm_mma<<<g1grid, TPB, GEMM_SMEM>>>(pz, pw1h, pw1l,
                                               b1 + l * TWOD_, ph1,
                                               N, D_, KPAD1, TWOD_,
                                               nullptr, nullptr);
        k_finalize<<<1, TWOD_>>>(g1 + l * TWOD_, be1 + l * TWOD_, N, TWOD_);
        k_wprep<<<wp2, TPB>>>(W2 + (size_t)l * TWOD_ * D_, pw2h, pw2l,
                              TWOD_, D_, KPAD2, NCP2);
        // z2 = relu(BN1(h1)) @ W2 + b2   (+ fused BN2 stats)
        k_gemm_mma<<<g2grid, TPB, GEMM_SMEM>>>(ph1, pw2h, pw2l,
                                               b2 + l * D_, pz2,
                                               N, TWOD_, KPAD2, D_,
                                               pA, pB);
        k_finalize<<<1, D_>>>(gamma + l * D_, beta + l * D_, N, D_);
        if (l < 4)
            k_apply<<<node_grid, TPB>>>(1, N, nullptr);
        else
            k_apply<<<node_grid, TPB>>>(0, N, out);
    }
}

// round 11
// speedup vs baseline: 2.2318x; 1.2416x over previous
#include <cuda_runtime.h>
#include <cuda_bf16.h>
#include <cstdint>

// Problem constants: N=50000, E=250000, D=300, L=5
#define D_    300
#define TWOD_ 600
#define NMAX  50000
#define DEG_CAP 64
#define KPAD1 320   // 300 -> 10 chunks of 32
#define KPAD2 608   // 600 -> 19 chunks of 32
#define KP2_1 (KPAD1 / 2)   // 160 packed pairs
#define KP2_2 (KPAD2 / 2)   // 304 packed pairs
#define NCP1  640   // 600 -> 5 tiles of 128 (zero-padded rows)
#define NCP2  384   // 300 -> 3 tiles of 128

// GEMM tiling (bf16 pairs: one uint32 = 2 bf16 along k)
#define BM 128
#define BN 128
#define BK 32
#define STRU 24                // smem row stride in uint32 (16 data + 8 pad)
#define TSZU (128 * STRU)
#define AHO_U 0
#define ALO_U TSZU
#define BHO_U (2 * TSZU)
#define BLO_U (3 * TSZU)
#define BUFSZ_U (4 * TSZU)
#define GEMM_SMEM (2 * BUFSZ_U * 4)   // 98304 bytes; 2 CTAs/SM fits 228KB

// ---- static scratch (no allocations allowed) ----
__device__ float g_h [NMAX * D_];
__device__ float g_h1[NMAX * TWOD_];
__device__ float g_z2[NMAX * D_];
__device__ float g_cs[TWOD_];
__device__ float g_cq[TWOD_];
__device__ float g_bnA[TWOD_];
__device__ float g_bnB[TWOD_];
__device__ int   g_fill[NMAX];
__device__ int   g_eid [NMAX * DEG_CAP];
// packed split activations (A operands), k-permuted bf16x2
__device__ uint32_t g_a1h[NMAX * KP2_1];
__device__ uint32_t g_a1l[NMAX * KP2_1];
__device__ uint32_t g_a2h[NMAX * KP2_2];
__device__ uint32_t g_a2l[NMAX * KP2_2];
// pre-transposed + bf16-split + pair-permuted + padded weights
__device__ uint32_t g_w1h[NCP1 * KP2_1];
__device__ uint32_t g_w1l[NCP1 * KP2_1];
__device__ uint32_t g_w2h[NCP2 * KP2_2];
__device__ uint32_t g_w2l[NCP2 * KP2_2];

// ============================================================
// helpers (baseline PTX only — safe under virtual arch compute_103)
// ============================================================
__device__ __forceinline__ uint32_t smem_u32(const void* p) {
    uint32_t a;
    asm("{ .reg .u64 t; cvta.to.shared.u64 t, %1; cvt.u32.u64 %0, t; }"
        : "=r"(a) : "l"(p));
    return a;
}
__device__ __forceinline__ void cp16p(uint32_t dst, const void* src, bool pred) {
    int sz = pred ? 16 : 0;
    asm volatile("cp.async.cg.shared.global [%0], [%1], 16, %2;"
                 :: "r"(dst), "l"(src), "r"(sz) : "memory");
}
__device__ __forceinline__ void cp_commit() {
    asm volatile("cp.async.commit_group;" ::: "memory");
}
__device__ __forceinline__ void cp_wait0() {
    asm volatile("cp.async.wait_group 0;" ::: "memory");
}
__device__ __forceinline__ void bf16s(float v, uint16_t& h, uint16_t& l) {
    __nv_bfloat16 hb = __float2bfloat16(v);
    float r = v - __bfloat162float(hb);
    __nv_bfloat16 lb = __float2bfloat16(r);
    h = __bfloat16_as_ushort(hb);
    l = __bfloat16_as_ushort(lb);
}
__device__ __forceinline__ void mma16(float* c,
                                      uint32_t a0, uint32_t a1, uint32_t a2, uint32_t a3,
                                      uint32_t b0, uint32_t b1) {
    asm volatile(
        "mma.sync.aligned.m16n8k16.row.col.f32.bf16.bf16.f32 "
        "{%0,%1,%2,%3}, {%4,%5,%6,%7}, {%8,%9}, {%0,%1,%2,%3};"
        : "+f"(c[0]), "+f"(c[1]), "+f"(c[2]), "+f"(c[3])
        : "r"(a0), "r"(a1), "r"(a2), "r"(a3), "r"(b0), "r"(b1));
}
// pack pair (a,b) at logical pair index kp2 into permuted split arrays
__device__ __forceinline__ void packw(uint32_t* __restrict__ Wh,
                                      uint32_t* __restrict__ Wl,
                                      size_t rowbase, int kp2, float a, float b) {
    int c  = kp2 >> 4;
    int pp = kp2 & 15;
    int pos = ((pp >> 3) << 3) + 2 * (pp & 3) + ((pp & 7) >> 2);
    size_t idx = rowbase + c * 16 + pos;
    uint16_t ha, la, hb, lb;
    bf16s(a, ha, la);
    bf16s(b, hb, lb);
    Wh[idx] = (uint32_t)ha | ((uint32_t)hb << 16);
    Wl[idx] = (uint32_t)la | ((uint32_t)lb << 16);
}

// ============================================================
// Atom encoder: h = sum of embeddings; zero bucket counters
// ============================================================
__global__ void k_atom(const int* __restrict__ x, const float* __restrict__ emb, int n)
{
    int idx = blockIdx.x * blockDim.x + threadIdx.x;
    if (idx < n) g_fill[idx] = 0;
    if (idx >= n * D_) return;
    int node = idx / D_;
    int d    = idx - node * D_;
    const int* xr = x + node * 9;
    float s = 0.f;
#pragma unroll
    for (int i = 0; i < 9; i++)
        s += emb[(i * 128 + xr[i]) * D_ + d];
    g_h[idx] = s;
}

// ============================================================
// Build inverted index
// ============================================================
__global__ void k_scatter(const int* __restrict__ ei, int E_)
{
    int e = blockIdx.x * blockDim.x + threadIdx.x;
    if (e >= E_) return;
    int dst = ei[E_ + e];
    int p = atomicAdd(&g_fill[dst], 1);
    if (p < DEG_CAP) g_eid[dst * DEG_CAP + p] = e;
}

// ============================================================
// Aggregation (atomic-free): warp per dst node.
// Emits z = (1+eps)h + sum relu(h[src]+e) DIRECTLY as packed split bf16
// (GEMM1's A operand); z fp32 is never materialized.
// ============================================================
__device__ __forceinline__ float4 msg4(float4 h, float4 a, float4 b, float4 c) {
    float4 m;
    m.x = fmaxf(h.x + a.x + b.x + c.x, 0.f);
    m.y = fmaxf(h.y + a.y + b.y + c.y, 0.f);
    m.z = fmaxf(h.z + a.z + b.z + c.z, 0.f);
    m.w = fmaxf(h.w + a.w + b.w + c.w, 0.f);
    return m;
}
__global__ void k_aggregate(const int* __restrict__ ei, const int* __restrict__ ea,
                            const float* __restrict__ bond,
                            const float* __restrict__ eps, int n, int layer)
{
    int w    = (blockIdx.x * blockDim.x + threadIdx.x) >> 5;
    int lane = threadIdx.x & 31;
    if (w >= n) return;
    int deg = g_fill[w];
    if (deg > DEG_CAP) deg = DEG_CAP;

    const float4* h4 = (const float4*)g_h;
    const float4* bl = (const float4*)(bond + (size_t)layer * 3 * 16 * D_);
    const int l2 = lane + 32, l3 = lane + 64;
    float4 a0 = make_float4(0.f, 0.f, 0.f, 0.f), a1 = a0, a2 = a0;

    const int* bucket = g_eid + (size_t)w * DEG_CAP;
    for (int p = 0; p < deg; ++p) {
        int eid = bucket[p];
        int src = ei[eid];
        int t3  = eid * 3;
        int c0 = ea[t3], c1 = ea[t3 + 1], c2 = ea[t3 + 2];
        const float4* hr = h4 + (size_t)src * 75;
        const float4* r0 = bl + c0 * 75;
        const float4* r1 = bl + (16 + c1) * 75;
        const float4* r2 = bl + (32 + c2) * 75;
        float4 m;
        m = msg4(hr[lane], r0[lane], r1[lane], r2[lane]);
        a0.x += m.x; a0.y += m.y; a0.z += m.z; a0.w += m.w;
        m = msg4(hr[l2], r0[l2], r1[l2], r2[l2]);
        a1.x += m.x; a1.y += m.y; a1.z += m.z; a1.w += m.w;
        if (l3 < 75) {
            m = msg4(hr[l3], r0[l3], r1[l3], r2[l3]);
            a2.x += m.x; a2.y += m.y; a2.z += m.z; a2.w += m.w;
        }
    }
    float ep = 1.f + eps[layer];
    const float4* hv = h4 + (size_t)w * 75;
    const size_t rowbase = (size_t)w * KP2_1;
    float4 h, o;
    h = hv[lane];
    o.x = fmaf(ep, h.x, a0.x); o.y = fmaf(ep, h.y, a0.y);
    o.z = fmaf(ep, h.z, a0.z); o.w = fmaf(ep, h.w, a0.w);
    packw(g_a1h, g_a1l, rowbase, 2 * lane,     o.x, o.y);
    packw(g_a1h, g_a1l, rowbase, 2 * lane + 1, o.z, o.w);
    h = hv[l2];
    o.x = fmaf(ep, h.x, a1.x); o.y = fmaf(ep, h.y, a1.y);
    o.z = fmaf(ep, h.z, a1.z); o.w = fmaf(ep, h.w, a1.w);
    packw(g_a1h, g_a1l, rowbase, 2 * l2,     o.x, o.y);
    packw(g_a1h, g_a1l, rowbase, 2 * l2 + 1, o.z, o.w);
    if (l3 < 75) {
        h = hv[l3];
        o.x = fmaf(ep, h.x, a2.x); o.y = fmaf(ep, h.y, a2.y);
        o.z = fmaf(ep, h.z, a2.z); o.w = fmaf(ep, h.w, a2.w);
        packw(g_a1h, g_a1l, rowbase, 2 * l3,     o.x, o.y);
        packw(g_a1h, g_a1l, rowbase, 2 * l3 + 1, o.z, o.w);
    }
    if (lane < KP2_1 - 150)   // zero-pad pairs 150..159 (k 300..319)
        packw(g_a1h, g_a1l, rowbase, 150 + lane, 0.f, 0.f);
}

// ============================================================
// A-split for GEMM2: relu(BN1(h1)) -> packed split bf16 (k-permuted, padded)
// ============================================================
__global__ void k_asplit(const float* __restrict__ X, int M, int K, int Kp2)
{
    int idx = blockIdx.x * blockDim.x + threadIdx.x;
    if (idx >= M * Kp2) return;
    int m   = idx / Kp2;
    int kp2 = idx - m * Kp2;
    int k0  = 2 * kp2;
    float a = 0.f, b = 0.f;
    if (k0 < K) {
        float2 v = *(const float2*)(X + (size_t)m * K + k0);
        a = fmaxf(fmaf(v.x, g_bnA[k0],     g_bnB[k0]),     0.f);
        b = fmaxf(fmaf(v.y, g_bnA[k0 + 1], g_bnB[k0 + 1]), 0.f);
    }
    packw(g_a2h, g_a2l, (size_t)m * Kp2, kp2, a, b);
}

// ============================================================
// Weight prep (transpose + split + permute + pad); zeroes fused stats
// ============================================================
__global__ void k_wprep(const float* __restrict__ W, uint32_t* __restrict__ Wh,
                        uint32_t* __restrict__ Wl, int K, int NC, int Kp2, int NCpad)
{
    int idx = blockIdx.x * blockDim.x + threadIdx.x;
    if (idx < TWOD_) { g_cs[idx] = 0.f; g_cq[idx] = 0.f; }
    if (idx >= NCpad * Kp2) return;
    int n   = idx / Kp2;
    int kp2 = idx - n * Kp2;
    int k0 = 2 * kp2;
    float v0 = (k0 < K && n < NC)     ? W[k0 * NC + n]       : 0.f;
    float v1 = (k0 + 1 < K && n < NC) ? W[(k0 + 1) * NC + n] : 0.f;
    packw(Wh, Wl, (size_t)n * Kp2, kp2, v0, v1);
}

// ============================================================
// 3xBF16 mma.sync GEMM, pure cp.async (A and B pre-packed), fused stats.
// 128x128x32 tiles, 8 warps (2x4), double-buffered, 2 CTAs/SM.
// ============================================================
__global__ void __launch_bounds__(256, 2) k_gemm_mma(
    const uint32_t* __restrict__ Ah, const uint32_t* __restrict__ Al,
    const uint32_t* __restrict__ Bh, const uint32_t* __restrict__ Bl,
    const float* __restrict__ bias, float* __restrict__ C,
    int M, int Kpad, int NC)
{
    extern __shared__ uint32_t smu[];
    const int tid = threadIdx.x;
    const int wid = tid >> 5, lid = tid & 31;
    const int g = lid >> 2, t4 = lid & 3;
    const int wm = wid >> 2, wn = wid & 3;
    const int bm = blockIdx.y * BM, bn = blockIdx.x * BN;
    const int nch = Kpad / BK;
    const int Kp2 = Kpad >> 1;

    const int lr = tid >> 1;
    const int lh = tid & 1;
    const bool aOk = (bm + lr) < M;
    const uint32_t* AhR = Ah + (size_t)(bm + lr) * Kp2 + lh * 8;
    const uint32_t* AlR = Al + (size_t)(bm + lr) * Kp2 + lh * 8;
    const uint32_t* BhR = Bh + (size_t)(bn + lr) * Kp2 + lh * 8;
    const uint32_t* BlR = Bl + (size_t)(bn + lr) * Kp2 + lh * 8;
    const uint32_t sm32 = smem_u32(smu);
    const uint32_t ld_off = (uint32_t)((lr * STRU + lh * 8) * 4);
    const uint32_t cpAH = sm32 + AHO_U * 4 + ld_off;
    const uint32_t cpAL = sm32 + ALO_U * 4 + ld_off;
    const uint32_t cpBH = sm32 + BHO_U * 4 + ld_off;
    const uint32_t cpBL = sm32 + BLO_U * 4 + ld_off;

    float acc[4][4][4];
#pragma unroll
    for (int i = 0; i < 4; i++)
#pragma unroll
        for (int j = 0; j < 4; j++)
#pragma unroll
            for (int k = 0; k < 4; k++) acc[i][j][k] = 0.f;

#define CP_CHUNK(BUFB, C0)                                                \
    {                                                                     \
        const uint32_t bo = (uint32_t)((BUFB) * 4);                       \
        const int co = (C0) * 16;                                         \
        cp16p(cpAH + bo,      AhR + co,     aOk);                         \
        cp16p(cpAH + bo + 16, AhR + co + 4, aOk);                         \
        cp16p(cpAL + bo,      AlR + co,     aOk);                         \
        cp16p(cpAL + bo + 16, AlR + co + 4, aOk);                         \
        cp16p(cpBH + bo,      BhR + co,     true);                        \
        cp16p(cpBH + bo + 16, BhR + co + 4, true);                        \
        cp16p(cpBL + bo,      BlR + co,     true);                        \
        cp16p(cpBL + bo + 16, BlR + co + 4, true);                        \
    }

    CP_CHUNK(0, 0);
    cp_commit();
    cp_wait0();
    __syncthreads();

    for (int c = 0; c < nch; ++c) {
        const int bufc = (c & 1) * BUFSZ_U;
        const int bufn = ((c + 1) & 1) * BUFSZ_U;
        if (c + 1 < nch) {
            CP_CHUNK(bufn, c + 1);
            cp_commit();
        }
        {
            const uint32_t* aH = smu + bufc + AHO_U;
            const uint32_t* aL = smu + bufc + ALO_U;
            const uint32_t* bH = smu + bufc + BHO_U;
            const uint32_t* bL = smu + bufc + BLO_U;
#pragma unroll
            for (int s = 0; s < 2; ++s) {
                const int ko = s * 8 + 2 * t4;
                uint2 fbh[4], fbl[4];
                uint2 ah0[4], ah1[4], al0[4], al1[4];
#pragma unroll
                for (int nt = 0; nt < 4; ++nt) {
                    const int n = wn * 32 + nt * 8 + g;
                    fbh[nt] = *(const uint2*)(bH + n * STRU + ko);
                    fbl[nt] = *(const uint2*)(bL + n * STRU + ko);
                }
#pragma unroll
                for (int mt = 0; mt < 4; ++mt) {
                    const int r0 = wm * 64 + mt * 16 + g;
                    ah0[mt] = *(const uint2*)(aH + r0 * STRU + ko);
                    ah1[mt] = *(const uint2*)(aH + (r0 + 8) * STRU + ko);
                    al0[mt] = *(const uint2*)(aL + r0 * STRU + ko);
                    al1[mt] = *(const uint2*)(aL + (r0 + 8) * STRU + ko);
                }
                // term-reordered: 16 independent MMAs between RAW reuses
#pragma unroll
                for (int mt = 0; mt < 4; ++mt)
#pragma unroll
                    for (int nt = 0; nt < 4; ++nt)
                        mma16(acc[mt][nt], ah0[mt].x, ah1[mt].x, ah0[mt].y, ah1[mt].y,
                              fbh[nt].x, fbh[nt].y);
#pragma unroll
                for (int mt = 0; mt < 4; ++mt)
#pragma unroll
                    for (int nt = 0; nt < 4; ++nt)
                        mma16(acc[mt][nt], ah0[mt].x, ah1[mt].x, ah0[mt].y, ah1[mt].y,
                              fbl[nt].x, fbl[nt].y);
#pragma unroll
                for (int mt = 0; mt < 4; ++mt)
#pragma unroll
                    for (int nt = 0; nt < 4; ++nt)
                        mma16(acc[mt][nt], al0[mt].x, al1[mt].x, al0[mt].y, al1[mt].y,
                              fbh[nt].x, fbh[nt].y);
            }
        }
        if (c + 1 < nch) cp_wait0();
        __syncthreads();
    }

    // ---- epilogue: +bias, stores, fused column stats ----
#pragma unroll
    for (int nt = 0; nt < 4; ++nt) {
        const int col = bn + wn * 32 + nt * 8 + 2 * t4;
        const bool cok = col < NC;
        const float b0 = cok ? bias[col]     : 0.f;
        const float b1 = cok ? bias[col + 1] : 0.f;
        float s0 = 0.f, s1 = 0.f, q0 = 0.f, q1 = 0.f;
#pragma unroll
        for (int mt = 0; mt < 4; ++mt) {
            const int r0g = bm + wm * 64 + mt * 16 + g;
            const float* a4 = acc[mt][nt];
            if (cok && r0g < M) {
                float v0 = a4[0] + b0, v1 = a4[1] + b1;
                *(float2*)(C + (size_t)r0g * NC + col) = make_float2(v0, v1);
                s0 += v0; q0 += v0 * v0;
                s1 += v1; q1 += v1 * v1;
            }
            if (cok && r0g + 8 < M) {
                float v2 = a4[2] + b0, v3 = a4[3] + b1;
                *(float2*)(C + (size_t)(r0g + 8) * NC + col) = make_float2(v2, v3);
                s0 += v2; q0 += v2 * v2;
                s1 += v3; q1 += v3 * v3;
            }
        }
#pragma unroll
        for (int m = 4; m <= 16; m <<= 1) {
            s0 += __shfl_xor_sync(0xffffffffu, s0, m);
            s1 += __shfl_xor_sync(0xffffffffu, s1, m);
            q0 += __shfl_xor_sync(0xffffffffu, q0, m);
            q1 += __shfl_xor_sync(0xffffffffu, q1, m);
        }
        if (cok && g == 0) {
            atomicAdd(&g_cs[col],     s0);
            atomicAdd(&g_cq[col],     q0);
            atomicAdd(&g_cs[col + 1], s1);
            atomicAdd(&g_cq[col + 1], q1);
        }
    }
#undef CP_CHUNK
}

// ============================================================
// BN finalize + apply
// ============================================================
__global__ void k_finalize(const float* __restrict__ g, const float* __restrict__ b,
                           int M, int C)
{
    int c = threadIdx.x;
    float mean = g_cs[c] / (float)M;
    float var  = g_cq[c] / (float)M - mean * mean;
    float a = g[c] * rsqrtf(var + 1e-5f);
    g_bnA[c] = a;
    g_bnB[c] = fmaf(-mean, a, b[c]);
}

__global__ void k_apply(int do_relu, int n, float* __restrict__ out)
{
    int idx = blockIdx.x * blockDim.x + threadIdx.x;
    if (idx >= n * D_) return;
    int c = idx % D_;
    float v = fmaf(g_z2[idx], g_bnA[c], g_bnB[c]);
    if (do_relu) v = fmaxf(v, 0.f);
    if (out) out[idx] = v;
    else     g_h[idx] = v;
}

// ============================================================
// Launch
// ============================================================
extern "C" void kernel_launch(void* const* d_in, const int* in_sizes, int n_in,
                              void* d_out, int out_size)
{
    const int*   x     = (const int*)  d_in[0];
    const int*   ei    = (const int*)  d_in[1];
    const int*   ea    = (const int*)  d_in[2];
    const float* atom  = (const float*)d_in[3];
    const float* bond  = (const float*)d_in[4];
    const float* eps   = (const float*)d_in[5];
    const float* W1    = (const float*)d_in[6];
    const float* b1    = (const float*)d_in[7];
    const float* g1    = (const float*)d_in[8];
    const float* be1   = (const float*)d_in[9];
    const float* W2    = (const float*)d_in[10];
    const float* b2    = (const float*)d_in[11];
    const float* gamma = (const float*)d_in[12];
    const float* beta  = (const float*)d_in[13];
    float* out = (float*)d_out;

    const int N = in_sizes[0] / 9;
    const int E = in_sizes[1] / 2;

    float *ph1, *pz2;
    uint32_t *pa1h, *pa1l, *pa2h, *pa2l, *pw1h, *pw1l, *pw2h, *pw2l;
    cudaGetSymbolAddress((void**)&ph1,  g_h1);
    cudaGetSymbolAddress((void**)&pz2,  g_z2);
    cudaGetSymbolAddress((void**)&pa1h, g_a1h);
    cudaGetSymbolAddress((void**)&pa1l, g_a1l);
    cudaGetSymbolAddress((void**)&pa2h, g_a2h);
    cudaGetSymbolAddress((void**)&pa2l, g_a2l);
    cudaGetSymbolAddress((void**)&pw1h, g_w1h);
    cudaGetSymbolAddress((void**)&pw1l, g_w1l);
    cudaGetSymbolAddress((void**)&pw2h, g_w2h);
    cudaGetSymbolAddress((void**)&pw2l, g_w2l);

    cudaFuncSetAttribute(k_gemm_mma, cudaFuncAttributeMaxDynamicSharedMemorySize,
                         GEMM_SMEM);

    const int TPB = 256;
    const int node_grid = (N * D_ + TPB - 1) / TPB;
    const int agg_grid  = (N + 7) / 8;
    const int asp_grid  = (N * KP2_2 + TPB - 1) / TPB;
    const dim3 g1grid(NCP1 / BN, (N + BM - 1) / BM);
    const dim3 g2grid(NCP2 / BN, (N + BM - 1) / BM);
    const int wp1 = (NCP1 * KP2_1 + TPB - 1) / TPB;
    const int wp2 = (NCP2 * KP2_2 + TPB - 1) / TPB;

    k_atom<<<node_grid, TPB>>>(x, atom, N);
    k_wprep<<<wp1, TPB>>>(W1, pw1h, pw1l, D_, TWOD_, KP2_1, NCP1);
    k_scatter<<<(E + TPB - 1) / TPB, TPB>>>(ei, E);

    for (int l = 0; l < 5; ++l) {
        if (l > 0)
            k_wprep<<<wp1, TPB>>>(W1 + (size_t)l * D_ * TWOD_, pw1h, pw1l,
                                  D_, TWOD_, KP2_1, NCP1);
        // z (packed split) = (1+eps)h + segment_sum(relu(h[src]+e))
        k_aggregate<<<agg_grid, TPB>>>(ei, ea, bond, eps, N, l);
        // h1 = z @ W1 + b1  (+ fused BN1 stats)
        k_gemm_mma<<<g1grid, TPB, GEMM_SMEM>>>(pa1h, pa1l, pw1h, pw1l,
                                               b1 + l * TWOD_, ph1,
                                               N, KPAD1, TWOD_);
        k_finalize<<<1, TWOD_>>>(g1 + l * TWOD_, be1 + l * TWOD_, N, TWOD_);
        // A2 = relu(BN1(h1)) packed split
        k_asplit<<<asp_grid, TPB>>>(ph1, N, TWOD_, KP2_2);
        k_wprep<<<wp2, TPB>>>(W2 + (size_t)l * TWOD_ * D_, pw2h, pw2l,
                              TWOD_, D_, KP2_2, NCP2);
        // z2 = A2 @ W2 + b2  (+ fused BN2 stats)
        k_gemm_mma<<<g2grid, TPB, GEMM_SMEM>>>(pa2h, pa2l, pw2h, pw2l,
                                               b2 + l * D_, pz2,
                                               N, KPAD2, D_);
        k_finalize<<<1, D_>>>(gamma + l * D_, beta + l * D_, N, D_);
        if (l < 4)
            k_apply<<<node_grid, TPB>>>(1, N, nullptr);
        else
            k_apply<<<node_grid, TPB>>>(0, N, out);
    }
}